// round 5
// baseline (speedup 1.0000x reference)
#include <cuda_runtime.h>
#include <mma.h>

using namespace nvcuda;

// Problem constants
#define B_    4
#define S_    4096
#define E_    2048
#define NH_   16
#define HD_   128
#define M_TOT (B_ * S_)   // 16384
#define BH_   (B_ * NH_)  // 64

// ---------------- scratch (static device allocations; no cudaMalloc) -------
__device__ float g_q[(size_t)M_TOT * E_];
__device__ float g_k[(size_t)M_TOT * E_];
__device__ float g_v[(size_t)M_TOT * E_];
__device__ float g_attn[(size_t)M_TOT * E_];
__device__ float g_p1[4 * BH_ * HD_ * HD_];  // partial K^T K  [chunk][bh][128][128]
__device__ float g_p2[4 * BH_ * HD_ * HD_];  // partial K^T V
__device__ float g_score[BH_ * HD_ * HD_];   // softmax(solve(...))

// ---------------- cp.async helpers ----------------------------------------
__device__ __forceinline__ void cp16(float* s, const float* g) {
    unsigned sa = (unsigned)__cvta_generic_to_shared(s);
    asm volatile("cp.async.cg.shared.global [%0], [%1], 16;" :: "r"(sa), "l"(g));
}
__device__ __forceinline__ void cp_commit() {
    asm volatile("cp.async.commit_group;");
}

// ---------------- generic GEMM: C[M,N] = A[M,K] @ W[K,N]  (tf32 wmma) ------
#define BM 128
#define BN 128
#define BK 32
#define LDAS 40
#define LDBS 136
#define GEMM_SMEM ((2 * BM * LDAS + 2 * BK * LDBS) * sizeof(float))

__global__ void gemm_tf32(const float* __restrict__ A, const float* __restrict__ W,
                          float* __restrict__ C, int M, int N, int K) {
    extern __shared__ float sm[];
    float* As = sm;
    float* Bs = sm + 2 * BM * LDAS;
    const int tid = threadIdx.x;
    const int bm = blockIdx.y, bn = blockIdx.x;
    const int wid = tid >> 5;
    const int wr = wid >> 1, wc = wid & 1;  // 4x2 warp grid; warp tile 32x64

    wmma::fragment<wmma::accumulator, 16, 16, 8, float> acc[2][4];
#pragma unroll
    for (int i = 0; i < 2; i++)
#pragma unroll
        for (int j = 0; j < 4; j++) wmma::fill_fragment(acc[i][j], 0.0f);

    const int KT = K / BK;

    auto load_tile = [&](int kt, int buf) {
        const float* Ag = A + (size_t)bm * BM * K + (size_t)kt * BK;
        float* Asb = As + buf * BM * LDAS;
#pragma unroll
        for (int p = 0; p < 4; p++) {
            int id = tid + p * 256;
            int r = id >> 3, c = (id & 7) << 2;  // 128 rows x 8 float4
            cp16(Asb + r * LDAS + c, Ag + (size_t)r * K + c);
        }
        const float* Wg = W + (size_t)kt * BK * N + (size_t)bn * BN;
        float* Bsb = Bs + buf * BK * LDBS;
#pragma unroll
        for (int p = 0; p < 4; p++) {
            int id = tid + p * 256;
            int r = id >> 5, c = (id & 31) << 2;  // 32 rows x 32 float4
            cp16(Bsb + r * LDBS + c, Wg + (size_t)r * N + c);
        }
    };

    load_tile(0, 0);
    cp_commit();

    for (int kt = 0; kt < KT; kt++) {
        int cur = kt & 1;
        if (kt + 1 < KT) {
            load_tile(kt + 1, cur ^ 1);
            cp_commit();
            asm volatile("cp.async.wait_group 1;");
        } else {
            asm volatile("cp.async.wait_group 0;");
        }
        __syncthreads();
        const float* Asb = As + cur * BM * LDAS;
        const float* Bsb = Bs + cur * BK * LDBS;
#pragma unroll
        for (int ks = 0; ks < BK; ks += 8) {
            wmma::fragment<wmma::matrix_a, 16, 16, 8, wmma::precision::tf32, wmma::row_major> af[2];
            wmma::fragment<wmma::matrix_b, 16, 16, 8, wmma::precision::tf32, wmma::row_major> bf[4];
#pragma unroll
            for (int i = 0; i < 2; i++) {
                wmma::load_matrix_sync(af[i], Asb + (wr * 32 + i * 16) * LDAS + ks, LDAS);
#pragma unroll
                for (int e = 0; e < af[i].num_elements; e++)
                    af[i].x[e] = wmma::__float_to_tf32(af[i].x[e]);
            }
#pragma unroll
            for (int j = 0; j < 4; j++) {
                wmma::load_matrix_sync(bf[j], Bsb + ks * LDBS + wc * 64 + j * 16, LDBS);
#pragma unroll
                for (int e = 0; e < bf[j].num_elements; e++)
                    bf[j].x[e] = wmma::__float_to_tf32(bf[j].x[e]);
            }
#pragma unroll
            for (int i = 0; i < 2; i++)
#pragma unroll
                for (int j = 0; j < 4; j++)
                    wmma::mma_sync(acc[i][j], af[i], bf[j], acc[i][j]);
        }
        __syncthreads();
    }

    float* Cg = C + (size_t)(bm * BM + wr * 32) * N + (size_t)bn * BN + wc * 64;
#pragma unroll
    for (int i = 0; i < 2; i++)
#pragma unroll
        for (int j = 0; j < 4; j++)
            wmma::store_matrix_sync(Cg + (size_t)i * 16 * N + j * 16, acc[i][j], N,
                                    wmma::mem_row_major);
}

// ---------------- bias add (in-place, vectorized) --------------------------
__global__ void bias_add(float* __restrict__ C, const float* __restrict__ bias, int n4tot) {
    int i = blockIdx.x * 256 + threadIdx.x;
    if (i >= n4tot) return;
    float4 c = reinterpret_cast<float4*>(C)[i];
    int nb = i & (E_ / 4 - 1);  // 512 float4 per row of 2048
    float4 b = reinterpret_cast<const float4*>(bias)[nb];
    c.x += b.x; c.y += b.y; c.z += b.z; c.w += b.w;
    reinterpret_cast<float4*>(C)[i] = c;
}

// ---------------- K^T K and K^T V partials (per bh, per S-chunk of 1024) ---
#define KKT_SMEM (2 * 32 * 136 * sizeof(float))
__global__ void kkt_ktv() {
    const int bh = blockIdx.x, chunk = blockIdx.y;
    const int b = bh >> 4, h = bh & 15;
    extern __shared__ float sm[];
    float* Ks = sm;
    float* Vs = sm + 32 * 136;
    const int tid = threadIdx.x;
    const int wid = tid >> 5, wr = wid >> 1, wc = wid & 1;

    const float* kbase = g_k + (size_t)b * S_ * E_ + (size_t)chunk * 1024 * E_ + h * HD_;
    const float* vbase = g_v + (size_t)b * S_ * E_ + (size_t)chunk * 1024 * E_ + h * HD_;

    wmma::fragment<wmma::accumulator, 16, 16, 8, float> acck[2][4], accv[2][4];
#pragma unroll
    for (int i = 0; i < 2; i++)
#pragma unroll
        for (int j = 0; j < 4; j++) {
            wmma::fill_fragment(acck[i][j], 0.0f);
            wmma::fill_fragment(accv[i][j], 0.0f);
        }

    for (int ss = 0; ss < 1024; ss += 32) {
        __syncthreads();
#pragma unroll
        for (int p = 0; p < 4; p++) {
            int id = tid + p * 256;
            int r = id >> 5, c = (id & 31) << 2;
            *reinterpret_cast<float4*>(Ks + r * 136 + c) =
                *reinterpret_cast<const float4*>(kbase + (size_t)(ss + r) * E_ + c);
            *reinterpret_cast<float4*>(Vs + r * 136 + c) =
                *reinterpret_cast<const float4*>(vbase + (size_t)(ss + r) * E_ + c);
        }
        __syncthreads();
#pragma unroll
        for (int ks = 0; ks < 32; ks += 8) {
            // A = K^T : col_major view of Ks[s][d]
            wmma::fragment<wmma::matrix_a, 16, 16, 8, wmma::precision::tf32, wmma::col_major> af[2];
#pragma unroll
            for (int i = 0; i < 2; i++) {
                wmma::load_matrix_sync(af[i], Ks + ks * 136 + wr * 32 + i * 16, 136);
#pragma unroll
                for (int e = 0; e < af[i].num_elements; e++)
                    af[i].x[e] = wmma::__float_to_tf32(af[i].x[e]);
            }
#pragma unroll
            for (int j = 0; j < 4; j++) {
                wmma::fragment<wmma::matrix_b, 16, 16, 8, wmma::precision::tf32, wmma::row_major> bf;
                wmma::load_matrix_sync(bf, Ks + ks * 136 + wc * 64 + j * 16, 136);
#pragma unroll
                for (int e = 0; e < bf.num_elements; e++) bf.x[e] = wmma::__float_to_tf32(bf.x[e]);
                wmma::mma_sync(acck[0][j], af[0], bf, acck[0][j]);
                wmma::mma_sync(acck[1][j], af[1], bf, acck[1][j]);
                wmma::load_matrix_sync(bf, Vs + ks * 136 + wc * 64 + j * 16, 136);
#pragma unroll
                for (int e = 0; e < bf.num_elements; e++) bf.x[e] = wmma::__float_to_tf32(bf.x[e]);
                wmma::mma_sync(accv[0][j], af[0], bf, accv[0][j]);
                wmma::mma_sync(accv[1][j], af[1], bf, accv[1][j]);
            }
        }
    }
    float* p1 = g_p1 + ((size_t)chunk * BH_ + bh) * (HD_ * HD_);
    float* p2 = g_p2 + ((size_t)chunk * BH_ + bh) * (HD_ * HD_);
#pragma unroll
    for (int i = 0; i < 2; i++)
#pragma unroll
        for (int j = 0; j < 4; j++) {
            wmma::store_matrix_sync(p1 + (wr * 32 + i * 16) * HD_ + wc * 64 + j * 16,
                                    acck[i][j], HD_, wmma::mem_row_major);
            wmma::store_matrix_sync(p2 + (wr * 32 + i * 16) * HD_ + wc * 64 + j * 16,
                                    accv[i][j], HD_, wmma::mem_row_major);
        }
}

// ---------------- Cholesky solve + softmax per (b,h) -----------------------
#define SOLVER_SMEM (2 * 128 * 129 * sizeof(float))
__global__ void solver(const float* __restrict__ alpha) {
    const int bh = blockIdx.x;
    const int tid = threadIdx.x;
    extern __shared__ float sm[];
    float* Am = sm;            // [128][129]  kk, factored in-place (lower = L)
    float* Bm = sm + 128 * 129;  // [128][129] rhs -> solution -> softmax
    const float a = alpha[0];

    // reduce 4 partials + alpha*I
    for (int i = tid; i < HD_ * HD_; i += 256) {
        int r = i >> 7, c = i & 127;
        float s1 = 0.f, s2 = 0.f;
#pragma unroll
        for (int ch = 0; ch < 4; ch++) {
            s1 += g_p1[((size_t)ch * BH_ + bh) * (HD_ * HD_) + i];
            s2 += g_p2[((size_t)ch * BH_ + bh) * (HD_ * HD_) + i];
        }
        Am[r * 129 + c] = s1 + ((r == c) ? a : 0.f);
        Bm[r * 129 + c] = s2;
    }
    __syncthreads();

    // Cholesky (full trailing update keeps symmetry; lower triangle holds L)
    for (int j = 0; j < HD_; j++) {
        if (tid == 0) Am[j * 129 + j] = sqrtf(Am[j * 129 + j]);
        __syncthreads();
        float dinv = 1.0f / Am[j * 129 + j];
        int n = 127 - j;
        for (int i = tid; i < n; i += 256) Am[(j + 1 + i) * 129 + j] *= dinv;
        __syncthreads();
        int tot = n * n;
        for (int t = tid; t < tot; t += 256) {
            int ri = j + 1 + t / n, ci = j + 1 + t % n;
            Am[ri * 129 + ci] -= Am[ri * 129 + j] * Am[ci * 129 + j];
        }
        __syncthreads();
    }

    // L y = B (forward), L^T x = y (backward); thread c owns column c
    if (tid < 128) {
        const int c = tid;
        for (int i = 0; i < 128; i++) {
            float t = Bm[i * 129 + c];
            for (int j2 = 0; j2 < i; j2++) t -= Am[i * 129 + j2] * Bm[j2 * 129 + c];
            Bm[i * 129 + c] = t / Am[i * 129 + i];
        }
        for (int i = 127; i >= 0; i--) {
            float t = Bm[i * 129 + c];
            for (int j2 = i + 1; j2 < 128; j2++) t -= Am[j2 * 129 + i] * Bm[j2 * 129 + c];
            Bm[i * 129 + c] = t / Am[i * 129 + i];
        }
    }
    __syncthreads();

    // row-wise softmax + store
    if (tid < 128) {
        const int r = tid;
        float m = -1e30f;
        for (int c = 0; c < 128; c++) m = fmaxf(m, Bm[r * 129 + c]);
        float s = 0.f;
        for (int c = 0; c < 128; c++) {
            float e = expf(Bm[r * 129 + c] - m);
            Bm[r * 129 + c] = e;
            s += e;
        }
        float inv = 1.0f / s;
        for (int c = 0; c < 128; c++)
            g_score[(size_t)bh * (HD_ * HD_) + r * HD_ + c] = Bm[r * 129 + c] * inv;
    }
}

// ---------------- out = Q @ score per (b,h), merged into [b,s,E] -----------
#define QS_SMEM (2 * 128 * 136 * sizeof(float))
__global__ void qscore() {
    const int st = blockIdx.x, h = blockIdx.y, b = blockIdx.z;
    extern __shared__ float sm[];
    float* Qs = sm;              // [128][136] rows s, cols d
    float* Sc = sm + 128 * 136;  // [128][136] rows d, cols e
    const int tid = threadIdx.x;
    const int wid = tid >> 5, wr = wid >> 1, wc = wid & 1;

    const float* qg = g_q + ((size_t)b * S_ + st * 128) * E_ + h * HD_;
    const float* sg = g_score + (size_t)(b * NH_ + h) * (HD_ * HD_);
#pragma unroll
    for (int p = 0; p < 16; p++) {
        int id = tid + p * 256;
        int r = id >> 5, c = (id & 31) << 2;
        *reinterpret_cast<float4*>(Qs + r * 136 + c) =
            *reinterpret_cast<const float4*>(qg + (size_t)r * E_ + c);
        *reinterpret_cast<float4*>(Sc + r * 136 + c) =
            *reinterpret_cast<const float4*>(sg + r * HD_ + c);
    }
    __syncthreads();

    wmma::fragment<wmma::accumulator, 16, 16, 8, float> acc[2][4];
#pragma unroll
    for (int i = 0; i < 2; i++)
#pragma unroll
        for (int j = 0; j < 4; j++) wmma::fill_fragment(acc[i][j], 0.0f);

#pragma unroll
    for (int ks = 0; ks < HD_; ks += 8) {
        wmma::fragment<wmma::matrix_a, 16, 16, 8, wmma::precision::tf32, wmma::row_major> af[2];
        wmma::fragment<wmma::matrix_b, 16, 16, 8, wmma::precision::tf32, wmma::row_major> bf[4];
#pragma unroll
        for (int i = 0; i < 2; i++) {
            wmma::load_matrix_sync(af[i], Qs + (wr * 32 + i * 16) * 136 + ks, 136);
#pragma unroll
            for (int e = 0; e < af[i].num_elements; e++)
                af[i].x[e] = wmma::__float_to_tf32(af[i].x[e]);
        }
#pragma unroll
        for (int j = 0; j < 4; j++) {
            wmma::load_matrix_sync(bf[j], Sc + ks * 136 + wc * 64 + j * 16, 136);
#pragma unroll
            for (int e = 0; e < bf[j].num_elements; e++)
                bf[j].x[e] = wmma::__float_to_tf32(bf[j].x[e]);
        }
#pragma unroll
        for (int i = 0; i < 2; i++)
#pragma unroll
            for (int j = 0; j < 4; j++)
                wmma::mma_sync(acc[i][j], af[i], bf[j], acc[i][j]);
    }

    float* og = g_attn + ((size_t)b * S_ + st * 128 + wr * 32) * E_ + h * HD_ + wc * 64;
#pragma unroll
    for (int i = 0; i < 2; i++)
#pragma unroll
        for (int j = 0; j < 4; j++)
            wmma::store_matrix_sync(og + (size_t)i * 16 * E_ + j * 16, acc[i][j], E_,
                                    wmma::mem_row_major);
}

// ---------------- host entry ------------------------------------------------
extern "C" void kernel_launch(void* const* d_in, const int* in_sizes, int n_in,
                              void* d_out, int out_size) {
    (void)in_sizes; (void)n_in; (void)out_size;
    const float* x     = (const float*)d_in[0];
    const float* alpha = (const float*)d_in[1];
    const float* Wq    = (const float*)d_in[2];
    const float* bq    = (const float*)d_in[3];
    const float* Wk    = (const float*)d_in[4];
    const float* bk    = (const float*)d_in[5];
    const float* Wv    = (const float*)d_in[6];
    const float* bv    = (const float*)d_in[7];
    const float* Wfc   = (const float*)d_in[8];
    const float* bfc   = (const float*)d_in[9];
    float* out = (float*)d_out;

    float *q, *k, *v, *attn;
    cudaGetSymbolAddress((void**)&q, g_q);
    cudaGetSymbolAddress((void**)&k, g_k);
    cudaGetSymbolAddress((void**)&v, g_v);
    cudaGetSymbolAddress((void**)&attn, g_attn);

    cudaFuncSetAttribute(gemm_tf32, cudaFuncAttributeMaxDynamicSharedMemorySize, GEMM_SMEM);
    cudaFuncSetAttribute(qscore, cudaFuncAttributeMaxDynamicSharedMemorySize, QS_SMEM);
    cudaFuncSetAttribute(solver, cudaFuncAttributeMaxDynamicSharedMemorySize, SOLVER_SMEM);

    dim3 gg(E_ / BN, M_TOT / BM);  // (16, 128)
    const int n4 = M_TOT * E_ / 4; // 8388608

    gemm_tf32<<<gg, 256, GEMM_SMEM>>>(x, Wq, q, M_TOT, E_, E_);
    gemm_tf32<<<gg, 256, GEMM_SMEM>>>(x, Wk, k, M_TOT, E_, E_);
    gemm_tf32<<<gg, 256, GEMM_SMEM>>>(x, Wv, v, M_TOT, E_, E_);
    bias_add<<<n4 / 256, 256>>>(q, bq, n4);
    bias_add<<<n4 / 256, 256>>>(k, bk, n4);
    bias_add<<<n4 / 256, 256>>>(v, bv, n4);

    kkt_ktv<<<dim3(BH_, 4), 256, KKT_SMEM>>>();
    solver<<<BH_, 256, SOLVER_SMEM>>>(alpha);
    qscore<<<dim3(S_ / 128, NH_, B_), 256, QS_SMEM>>>();

    gemm_tf32<<<gg, 256, GEMM_SMEM>>>(attn, Wfc, out, M_TOT, E_, E_);
    bias_add<<<n4 / 256, 256>>>(out, bfc, n4);
}

// round 9
// speedup vs baseline: 1.2383x; 1.2383x over previous
#include <cuda_runtime.h>
#include <mma.h>
#include <cstdint>

using namespace nvcuda;

// Problem constants
#define B_    4
#define S_    4096
#define E_    2048
#define NH_   16
#define HD_   128
#define M_TOT (B_ * S_)   // 16384
#define BH_   (B_ * NH_)  // 64

// ---------------- scratch (static device allocations; no cudaMalloc) -------
__device__ float g_G  [(size_t)B_ * E_ * E_];   // per-batch X^T X
__device__ float g_yk [(size_t)B_ * E_ * E_];   // G @ Wk
__device__ float g_yv [(size_t)B_ * E_ * E_];   // G @ Wv
__device__ float g_wqs[(size_t)B_ * E_ * E_];   // Wq @ blockdiag(score)
__device__ float g_w2 [(size_t)B_ * E_ * E_];   // Wqs @ Wfc
__device__ float g_s  [B_ * E_];                // column sums of X per batch
__device__ float g_bqs[B_ * E_];                // score^T bq (concatenated heads)
__device__ float g_b2 [B_ * E_];                // final fused bias
__device__ float g_p1 [4 * BH_ * HD_ * HD_];    // partial Wk^T G Wk
__device__ float g_p2 [4 * BH_ * HD_ * HD_];    // partial Wk^T G Wv
__device__ float g_score[BH_ * HD_ * HD_];      // softmax(solve(...))

// ---------------- cp.async helpers ----------------------------------------
__device__ __forceinline__ void cp16(float* s, const float* g) {
    unsigned sa = (unsigned)__cvta_generic_to_shared(s);
    asm volatile("cp.async.cg.shared.global [%0], [%1], 16;" :: "r"(sa), "l"(g));
}
__device__ __forceinline__ void cp_commit() {
    asm volatile("cp.async.commit_group;");
}

// ================= generic batched GEMM: C[z] = A[z] @ W[z]  (tf32 wmma) ===
#define BM 128
#define BN 128
#define BK 32
#define LDAS 40
#define LDBS 136
#define GEMM_SMEM ((2 * BM * LDAS + 2 * BK * LDBS) * sizeof(float))

__global__ void gemm_tf32(const float* __restrict__ A, const float* __restrict__ W,
                          float* __restrict__ C, int M, int N, int K,
                          long long sA, long long sB, long long sC) {
    A += (long long)blockIdx.z * sA;
    W += (long long)blockIdx.z * sB;
    C += (long long)blockIdx.z * sC;
    extern __shared__ float sm[];
    float* As = sm;
    float* Bs = sm + 2 * BM * LDAS;
    const int tid = threadIdx.x;
    const int bm = blockIdx.y, bn = blockIdx.x;
    const int wid = tid >> 5;
    const int wr = wid >> 1, wc = wid & 1;  // 4x2 warp grid; warp tile 32x64

    wmma::fragment<wmma::accumulator, 16, 16, 8, float> acc[2][4];
#pragma unroll
    for (int i = 0; i < 2; i++)
#pragma unroll
        for (int j = 0; j < 4; j++) wmma::fill_fragment(acc[i][j], 0.0f);

    const int KT = K / BK;

    auto load_tile = [&](int kt, int buf) {
        const float* Ag = A + (size_t)bm * BM * K + (size_t)kt * BK;
        float* Asb = As + buf * BM * LDAS;
#pragma unroll
        for (int p = 0; p < 4; p++) {
            int id = tid + p * 256;
            int r = id >> 3, c = (id & 7) << 2;
            cp16(Asb + r * LDAS + c, Ag + (size_t)r * K + c);
        }
        const float* Wg = W + (size_t)kt * BK * N + (size_t)bn * BN;
        float* Bsb = Bs + buf * BK * LDBS;
#pragma unroll
        for (int p = 0; p < 4; p++) {
            int id = tid + p * 256;
            int r = id >> 5, c = (id & 31) << 2;
            cp16(Bsb + r * LDBS + c, Wg + (size_t)r * N + c);
        }
    };

    load_tile(0, 0);
    cp_commit();

    for (int kt = 0; kt < KT; kt++) {
        int cur = kt & 1;
        if (kt + 1 < KT) {
            load_tile(kt + 1, cur ^ 1);
            cp_commit();
            asm volatile("cp.async.wait_group 1;");
        } else {
            asm volatile("cp.async.wait_group 0;");
        }
        __syncthreads();
        const float* Asb = As + cur * BM * LDAS;
        const float* Bsb = Bs + cur * BK * LDBS;
#pragma unroll
        for (int ks = 0; ks < BK; ks += 8) {
            wmma::fragment<wmma::matrix_a, 16, 16, 8, wmma::precision::tf32, wmma::row_major> af[2];
            wmma::fragment<wmma::matrix_b, 16, 16, 8, wmma::precision::tf32, wmma::row_major> bf[4];
#pragma unroll
            for (int i = 0; i < 2; i++) {
                wmma::load_matrix_sync(af[i], Asb + (wr * 32 + i * 16) * LDAS + ks, LDAS);
#pragma unroll
                for (int e = 0; e < af[i].num_elements; e++)
                    af[i].x[e] = wmma::__float_to_tf32(af[i].x[e]);
            }
#pragma unroll
            for (int j = 0; j < 4; j++) {
                wmma::load_matrix_sync(bf[j], Bsb + ks * LDBS + wc * 64 + j * 16, LDBS);
#pragma unroll
                for (int e = 0; e < bf[j].num_elements; e++)
                    bf[j].x[e] = wmma::__float_to_tf32(bf[j].x[e]);
            }
#pragma unroll
            for (int i = 0; i < 2; i++)
#pragma unroll
                for (int j = 0; j < 4; j++)
                    wmma::mma_sync(acc[i][j], af[i], bf[j], acc[i][j]);
        }
        __syncthreads();
    }

    float* Cg = C + (size_t)(bm * BM + wr * 32) * N + (size_t)bn * BN + wc * 64;
#pragma unroll
    for (int i = 0; i < 2; i++)
#pragma unroll
        for (int j = 0; j < 4; j++)
            wmma::store_matrix_sync(Cg + (size_t)i * 16 * N + j * 16, acc[i][j], N,
                                    wmma::mem_row_major);
}

// ---------------- column sums: s[b][e] = sum_m x[b][m][e] -------------------
__global__ void colsum(const float* __restrict__ x) {
    __shared__ float red[256];
    const int tid = threadIdx.x;
    const int tx = tid & 31, ty = tid >> 5;
    const int e = blockIdx.x * 32 + tx;
    const int b = blockIdx.y;
    const float* xb = x + (size_t)b * S_ * E_ + e;
    float acc = 0.f;
    for (int m = ty; m < S_; m += 8) acc += xb[(size_t)m * E_];
    red[ty * 32 + tx] = acc;
    __syncthreads();
    if (ty == 0) {
        float t = 0.f;
#pragma unroll
        for (int i = 0; i < 8; i++) t += red[i * 32 + tx];
        g_s[b * E_ + e] = t;
    }
}

// ---------------- G = X^T X (upper tiles; transposed store fills lower) ----
#define SYRK_SMEM (2 * 32 * 136 * sizeof(float))
__global__ void syrk_xtx(const float* __restrict__ x) {
    int rem = blockIdx.x, i = 0;
    while (rem >= 16 - i) { rem -= (16 - i); i++; }
    const int j = i + rem;
    const int b = blockIdx.y;
    extern __shared__ float sm[];
    float* As = sm;
    float* Bs = sm + 32 * 136;
    const int tid = threadIdx.x;
    const int wid = tid >> 5, wr = wid >> 1, wc = wid & 1;

    const float* ai = x + (size_t)b * S_ * E_ + i * 128;
    const float* bj = x + (size_t)b * S_ * E_ + j * 128;

    wmma::fragment<wmma::accumulator, 16, 16, 8, float> acc[2][4];
#pragma unroll
    for (int p = 0; p < 2; p++)
#pragma unroll
        for (int q = 0; q < 4; q++) wmma::fill_fragment(acc[p][q], 0.0f);

    for (int ss = 0; ss < S_; ss += 32) {
        __syncthreads();
#pragma unroll
        for (int p = 0; p < 4; p++) {
            int id = tid + p * 256;
            int r = id >> 5, c = (id & 31) << 2;
            *reinterpret_cast<float4*>(As + r * 136 + c) =
                *reinterpret_cast<const float4*>(ai + (size_t)(ss + r) * E_ + c);
            *reinterpret_cast<float4*>(Bs + r * 136 + c) =
                *reinterpret_cast<const float4*>(bj + (size_t)(ss + r) * E_ + c);
        }
        __syncthreads();
#pragma unroll
        for (int ks = 0; ks < 32; ks += 8) {
            wmma::fragment<wmma::matrix_a, 16, 16, 8, wmma::precision::tf32, wmma::col_major> af[2];
#pragma unroll
            for (int p = 0; p < 2; p++) {
                wmma::load_matrix_sync(af[p], As + ks * 136 + wr * 32 + p * 16, 136);
#pragma unroll
                for (int e = 0; e < af[p].num_elements; e++)
                    af[p].x[e] = wmma::__float_to_tf32(af[p].x[e]);
            }
#pragma unroll
            for (int q = 0; q < 4; q++) {
                wmma::fragment<wmma::matrix_b, 16, 16, 8, wmma::precision::tf32, wmma::row_major> bf;
                wmma::load_matrix_sync(bf, Bs + ks * 136 + wc * 64 + q * 16, 136);
#pragma unroll
                for (int e = 0; e < bf.num_elements; e++) bf.x[e] = wmma::__float_to_tf32(bf.x[e]);
                wmma::mma_sync(acc[0][q], af[0], bf, acc[0][q]);
                wmma::mma_sync(acc[1][q], af[1], bf, acc[1][q]);
            }
        }
    }

    float* Gb = g_G + (size_t)b * E_ * E_;
#pragma unroll
    for (int p = 0; p < 2; p++)
#pragma unroll
        for (int q = 0; q < 4; q++) {
            int rr = wr * 32 + p * 16, cc = wc * 64 + q * 16;
            wmma::store_matrix_sync(Gb + (size_t)(i * 128 + rr) * E_ + j * 128 + cc,
                                    acc[p][q], E_, wmma::mem_row_major);
            if (i != j)
                wmma::store_matrix_sync(Gb + (size_t)(j * 128 + cc) * E_ + i * 128 + rr,
                                        acc[p][q], E_, wmma::mem_col_major);
        }
}

// --------- per-head raw mats: p1 = Wk_h^T Yk[:,h], p2 = Wk_h^T Yv[:,h] -----
#define HB_SMEM (3 * 32 * 136 * sizeof(float))
__global__ void head_build(const float* __restrict__ Wk) {
    const int bh = blockIdx.x, chunk = blockIdx.y;
    const int b = bh >> 4, h = bh & 15;
    extern __shared__ float sm[];
    float* Ws  = sm;
    float* Yks = sm + 32 * 136;
    float* Yvs = sm + 2 * 32 * 136;
    const int tid = threadIdx.x;
    const int wid = tid >> 5, wr = wid >> 1, wc = wid & 1;

    const float* wbase = Wk + h * 128;
    const float* ykb = g_yk + (size_t)b * E_ * E_ + h * 128;
    const float* yvb = g_yv + (size_t)b * E_ * E_ + h * 128;
    const int k0 = chunk * 512;

    wmma::fragment<wmma::accumulator, 16, 16, 8, float> acck[2][4], accv[2][4];
#pragma unroll
    for (int p = 0; p < 2; p++)
#pragma unroll
        for (int q = 0; q < 4; q++) {
            wmma::fill_fragment(acck[p][q], 0.0f);
            wmma::fill_fragment(accv[p][q], 0.0f);
        }

    for (int ss = 0; ss < 512; ss += 32) {
        __syncthreads();
#pragma unroll
        for (int p = 0; p < 4; p++) {
            int id = tid + p * 256;
            int r = id >> 5, c = (id & 31) << 2;
            size_t row = (size_t)(k0 + ss + r) * E_;
            *reinterpret_cast<float4*>(Ws  + r * 136 + c) =
                *reinterpret_cast<const float4*>(wbase + row + c);
            *reinterpret_cast<float4*>(Yks + r * 136 + c) =
                *reinterpret_cast<const float4*>(ykb + row + c);
            *reinterpret_cast<float4*>(Yvs + r * 136 + c) =
                *reinterpret_cast<const float4*>(yvb + row + c);
        }
        __syncthreads();
#pragma unroll
        for (int ks = 0; ks < 32; ks += 8) {
            wmma::fragment<wmma::matrix_a, 16, 16, 8, wmma::precision::tf32, wmma::col_major> af[2];
#pragma unroll
            for (int p = 0; p < 2; p++) {
                wmma::load_matrix_sync(af[p], Ws + ks * 136 + wr * 32 + p * 16, 136);
#pragma unroll
                for (int e = 0; e < af[p].num_elements; e++)
                    af[p].x[e] = wmma::__float_to_tf32(af[p].x[e]);
            }
#pragma unroll
            for (int q = 0; q < 4; q++) {
                wmma::fragment<wmma::matrix_b, 16, 16, 8, wmma::precision::tf32, wmma::row_major> bf;
                wmma::load_matrix_sync(bf, Yks + ks * 136 + wc * 64 + q * 16, 136);
#pragma unroll
                for (int e = 0; e < bf.num_elements; e++) bf.x[e] = wmma::__float_to_tf32(bf.x[e]);
                wmma::mma_sync(acck[0][q], af[0], bf, acck[0][q]);
                wmma::mma_sync(acck[1][q], af[1], bf, acck[1][q]);
                wmma::load_matrix_sync(bf, Yvs + ks * 136 + wc * 64 + q * 16, 136);
#pragma unroll
                for (int e = 0; e < bf.num_elements; e++) bf.x[e] = wmma::__float_to_tf32(bf.x[e]);
                wmma::mma_sync(accv[0][q], af[0], bf, accv[0][q]);
                wmma::mma_sync(accv[1][q], af[1], bf, accv[1][q]);
            }
        }
    }
    float* p1 = g_p1 + ((size_t)chunk * BH_ + bh) * (HD_ * HD_);
    float* p2 = g_p2 + ((size_t)chunk * BH_ + bh) * (HD_ * HD_);
#pragma unroll
    for (int p = 0; p < 2; p++)
#pragma unroll
        for (int q = 0; q < 4; q++) {
            wmma::store_matrix_sync(p1 + (wr * 32 + p * 16) * HD_ + wc * 64 + q * 16,
                                    acck[p][q], HD_, wmma::mem_row_major);
            wmma::store_matrix_sync(p2 + (wr * 32 + p * 16) * HD_ + wc * 64 + q * 16,
                                    accv[p][q], HD_, wmma::mem_row_major);
        }
}

// -------- solver: bias rank-1s + alpha*I, Cholesky solve, softmax, bqs -----
#define SOLVER_SMEM ((2 * 128 * 129 + 6 * 128 + 512) * sizeof(float))
__global__ void solver(const float* __restrict__ alpha,
                       const float* __restrict__ Wk, const float* __restrict__ Wv,
                       const float* __restrict__ bk, const float* __restrict__ bv,
                       const float* __restrict__ bq) {
    const int bh = blockIdx.x;
    const int b = bh >> 4, h = bh & 15;
    const int tid = threadIdx.x;
    extern __shared__ float sm[];
    float* Am  = sm;
    float* Bm  = Am + 128 * 129;
    float* uK  = Bm + 128 * 129;
    float* uV  = uK + 128;
    float* bks = uV + 128;
    float* bvs = bks + 128;
    float* bqv = bvs + 128;
    float* sinv = bqv + 128;
    float* uKp = sinv + 128;   // [2][128]
    float* uVp = uKp + 256;    // [2][128]

    // u vectors: uK = Wk_h^T s,  uV = Wv_h^T s  (split K over 2 thread groups)
    {
        const int c = tid & 127, half = tid >> 7;
        const float* sb = g_s + b * E_;
        const float* pk = Wk + h * 128 + c;
        const float* pv = Wv + h * 128 + c;
        float ak = 0.f, av = 0.f;
#pragma unroll 4
        for (int k = half * 1024; k < half * 1024 + 1024; k++) {
            float sv = sb[k];
            ak += pk[(size_t)k * E_] * sv;
            av += pv[(size_t)k * E_] * sv;
        }
        uKp[half * 128 + c] = ak;
        uVp[half * 128 + c] = av;
        if (tid < 128) {
            bks[tid] = bk[h * 128 + tid];
            bvs[tid] = bv[h * 128 + tid];
            bqv[tid] = bq[h * 128 + tid];
        }
    }
    __syncthreads();
    if (tid < 128) {
        uK[tid] = uKp[tid] + uKp[128 + tid];
        uV[tid] = uVp[tid] + uVp[128 + tid];
    }
    __syncthreads();

    const float a = alpha[0];
    for (int i = tid; i < HD_ * HD_; i += 256) {
        int r = i >> 7, c = i & 127;
        float s1 = 0.f, s2 = 0.f;
#pragma unroll
        for (int ch = 0; ch < 4; ch++) {
            s1 += g_p1[((size_t)ch * BH_ + bh) * (HD_ * HD_) + i];
            s2 += g_p2[((size_t)ch * BH_ + bh) * (HD_ * HD_) + i];
        }
        Am[r * 129 + c] = s1 + uK[r] * bks[c] + bks[r] * uK[c]
                          + (float)S_ * bks[r] * bks[c] + ((r == c) ? a : 0.f);
        Bm[r * 129 + c] = s2 + uK[r] * bvs[c] + bks[r] * uV[c]
                          + (float)S_ * bks[r] * bvs[c];
    }
    __syncthreads();

    // Cholesky (lower triangle holds L)
    for (int j = 0; j < HD_; j++) {
        if (tid == 0) Am[j * 129 + j] = sqrtf(Am[j * 129 + j]);
        __syncthreads();
        float dinv = 1.0f / Am[j * 129 + j];
        int n = 127 - j;
        for (int i = tid; i < n; i += 256) Am[(j + 1 + i) * 129 + j] *= dinv;
        __syncthreads();
        int tot = n * n;
        for (int t = tid; t < tot; t += 256) {
            int ri = j + 1 + t / n, ci = j + 1 + t % n;
            Am[ri * 129 + ci] -= Am[ri * 129 + j] * Am[ci * 129 + j];
        }
        __syncthreads();
    }

    // L y = B (forward), L^T x = y (backward); thread c owns column c
    if (tid < 128) {
        const int c = tid;
        for (int i = 0; i < 128; i++) {
            float t = Bm[i * 129 + c];
            for (int j2 = 0; j2 < i; j2++) t -= Am[i * 129 + j2] * Bm[j2 * 129 + c];
            Bm[i * 129 + c] = t / Am[i * 129 + i];
        }
        for (int i = 127; i >= 0; i--) {
            float t = Bm[i * 129 + c];
            for (int j2 = i + 1; j2 < 128; j2++) t -= Am[j2 * 129 + i] * Bm[j2 * 129 + c];
            Bm[i * 129 + c] = t / Am[i * 129 + i];
        }
    }
    __syncthreads();

    // row softmax (Bm keeps exp values; sinv[r] = 1/rowsum); store score
    if (tid < 128) {
        const int r = tid;
        float m = -1e30f;
        for (int c = 0; c < 128; c++) m = fmaxf(m, Bm[r * 129 + c]);
        float s = 0.f;
        for (int c = 0; c < 128; c++) {
            float e = expf(Bm[r * 129 + c] - m);
            Bm[r * 129 + c] = e;
            s += e;
        }
        float inv = 1.0f / s;
        sinv[r] = inv;
        for (int c = 0; c < 128; c++)
            g_score[(size_t)bh * (HD_ * HD_) + r * HD_ + c] = Bm[r * 129 + c] * inv;
    }
    __syncthreads();

    // bqs[c] = sum_r bq[r] * score[r][c]
    if (tid < 128) {
        const int c = tid;
        float acc = 0.f;
        for (int r = 0; r < 128; r++) acc += bqv[r] * Bm[r * 129 + c] * sinv[r];
        g_bqs[b * E_ + h * 128 + c] = acc;
    }
}

// ------ Wqs[:, hblk] = Wq[:, hblk] @ score_bh  (fp32 SIMT, exact-ish) ------
#define WQS_SMEM (128 * 132 * sizeof(float))
__global__ void wqs_kernel(const float* __restrict__ Wq) {
    const int bx = blockIdx.x, h = blockIdx.y, b = blockIdx.z;
    extern __shared__ float sc[];  // [128][132]
    const int tid = threadIdx.x;
    const float* sg = g_score + (size_t)(b * NH_ + h) * (HD_ * HD_);
    for (int i = tid; i < 128 * 128; i += 256) {
        int r = i >> 7, c = i & 127;
        sc[r * 132 + c] = sg[i];
    }
    __syncthreads();

    const int pr = tid >> 4, pc = tid & 15;  // 16x16 patches of 8x8
    const float* wrow = Wq + (size_t)(bx * 128 + pr * 8) * E_ + h * 128;
    float acc[8][8];
#pragma unroll
    for (int i = 0; i < 8; i++)
#pragma unroll
        for (int j = 0; j < 8; j++) acc[i][j] = 0.f;

    for (int k = 0; k < 128; k++) {
        float w8[8];
#pragma unroll
        for (int i = 0; i < 8; i++) w8[i] = wrow[(size_t)i * E_ + k];
        float4 s0 = *reinterpret_cast<const float4*>(&sc[k * 132 + pc * 8]);
        float4 s1 = *reinterpret_cast<const float4*>(&sc[k * 132 + pc * 8 + 4]);
        float s8[8] = {s0.x, s0.y, s0.z, s0.w, s1.x, s1.y, s1.z, s1.w};
#pragma unroll
        for (int i = 0; i < 8; i++)
#pragma unroll
            for (int j = 0; j < 8; j++) acc[i][j] += w8[i] * s8[j];
    }

    float* og = g_wqs + (size_t)b * E_ * E_ + (size_t)(bx * 128 + pr * 8) * E_ + h * 128 + pc * 8;
#pragma unroll
    for (int i = 0; i < 8; i++) {
        *reinterpret_cast<float4*>(og + (size_t)i * E_) =
            make_float4(acc[i][0], acc[i][1], acc[i][2], acc[i][3]);
        *reinterpret_cast<float4*>(og + (size_t)i * E_ + 4) =
            make_float4(acc[i][4], acc[i][5], acc[i][6], acc[i][7]);
    }
}

// ------ b2[b][n] = sum_k bqs[b][k] * Wfc[k][n] + bfc[n] --------------------
__global__ void b2_build(const float* __restrict__ Wfc, const float* __restrict__ bfc) {
    const int n = blockIdx.x * 256 + threadIdx.x;
    const int b = blockIdx.y;
    const float* bqs = g_bqs + b * E_;
    float acc = bfc[n];
    for (int k = 0; k < E_; k++) acc += bqs[k] * Wfc[(size_t)k * E_ + n];
    g_b2[b * E_ + n] = acc;
}

// ------ out += b2 (per batch) ----------------------------------------------
__global__ void bias_add_b2(float* __restrict__ C) {
    int i = blockIdx.x * 256 + threadIdx.x;
    int batch = i >> 21;            // S_*E_/4 = 2^21 float4 per batch
    int nb = i & (E_ / 4 - 1);
    float4 c = reinterpret_cast<float4*>(C)[i];
    float4 bb = reinterpret_cast<const float4*>(g_b2 + batch * E_)[nb];
    c.x += bb.x; c.y += bb.y; c.z += bb.z; c.w += bb.w;
    reinterpret_cast<float4*>(C)[i] = c;
}

// ---------------- host entry ------------------------------------------------
extern "C" void kernel_launch(void* const* d_in, const int* in_sizes, int n_in,
                              void* d_out, int out_size) {
    (void)in_sizes; (void)n_in; (void)out_size;
    const float* x     = (const float*)d_in[0];
    const float* alpha = (const float*)d_in[1];
    const float* Wq    = (const float*)d_in[2];
    const float* bq    = (const float*)d_in[3];
    const float* Wk    = (const float*)d_in[4];
    const float* bk    = (const float*)d_in[5];
    const float* Wv    = (const float*)d_in[6];
    const float* bv    = (const float*)d_in[7];
    const float* Wfc   = (const float*)d_in[8];
    const float* bfc   = (const float*)d_in[9];
    float* out = (float*)d_out;

    float *G, *yk, *yv, *wqs, *w2;
    cudaGetSymbolAddress((void**)&G,   g_G);
    cudaGetSymbolAddress((void**)&yk,  g_yk);
    cudaGetSymbolAddress((void**)&yv,  g_yv);
    cudaGetSymbolAddress((void**)&wqs, g_wqs);
    cudaGetSymbolAddress((void**)&w2,  g_w2);

    cudaFuncSetAttribute(gemm_tf32, cudaFuncAttributeMaxDynamicSharedMemorySize, GEMM_SMEM);
    cudaFuncSetAttribute(syrk_xtx, cudaFuncAttributeMaxDynamicSharedMemorySize, SYRK_SMEM);
    cudaFuncSetAttribute(head_build, cudaFuncAttributeMaxDynamicSharedMemorySize, HB_SMEM);
    cudaFuncSetAttribute(solver, cudaFuncAttributeMaxDynamicSharedMemorySize, SOLVER_SMEM);
    cudaFuncSetAttribute(wqs_kernel, cudaFuncAttributeMaxDynamicSharedMemorySize, WQS_SMEM);

    const long long EE = (long long)E_ * E_;
    const long long SE = (long long)S_ * E_;

    // K/V side via G = X^T X
    colsum<<<dim3(E_ / 32, B_), 256>>>(x);
    syrk_xtx<<<dim3(136, B_), 256, SYRK_SMEM>>>(x);
    gemm_tf32<<<dim3(16, 16, B_), 256, GEMM_SMEM>>>(G, Wk, yk, E_, E_, E_, EE, 0, EE);
    gemm_tf32<<<dim3(16, 16, B_), 256, GEMM_SMEM>>>(G, Wv, yv, E_, E_, E_, EE, 0, EE);
    head_build<<<dim3(BH_, 4), 256, HB_SMEM>>>(Wk);
    solver<<<BH_, 256, SOLVER_SMEM>>>(alpha, Wk, Wv, bk, bv, bq);

    // Q side collapsed: out = X @ (Wq BD(score) Wfc) + b2
    wqs_kernel<<<dim3(16, NH_, B_), 256, WQS_SMEM>>>(Wq);
    b2_build<<<dim3(E_ / 256, B_), 256>>>(Wfc, bfc);
    gemm_tf32<<<dim3(16, 16, B_), 256, GEMM_SMEM>>>(wqs, Wfc, w2, E_, E_, E_, EE, 0, EE);
    gemm_tf32<<<dim3(16, 32, B_), 256, GEMM_SMEM>>>(x, w2, out, S_, E_, E_, SE, EE, SE);
    bias_add_b2<<<(M_TOT * E_ / 4) / 256, 256>>>(out);
}

// round 10
// speedup vs baseline: 1.3524x; 1.0922x over previous
#include <cuda_runtime.h>
#include <mma.h>
#include <cstdint>

using namespace nvcuda;

// Problem constants
#define B_    4
#define S_    4096
#define E_    2048
#define NH_   16
#define HD_   128
#define M_TOT (B_ * S_)   // 16384
#define BH_   (B_ * NH_)  // 64

// ---------------- scratch (static device allocations; no cudaMalloc) -------
__device__ float g_G  [(size_t)B_ * E_ * E_];   // per-batch X^T X (tf32-rounded)
__device__ float g_yk [(size_t)B_ * E_ * E_];   // G @ Wk (rounded)
__device__ float g_yv [(size_t)B_ * E_ * E_];   // G @ Wv (rounded)
__device__ float g_wqs[(size_t)B_ * E_ * E_];   // Wq @ blockdiag(score) (rounded)
__device__ float g_w2 [(size_t)B_ * E_ * E_];   // Wqs @ Wfc (rounded)
__device__ float g_xr [(size_t)M_TOT * E_];     // tf32-rounded x
__device__ float g_wr [(size_t)3 * E_ * E_];    // rounded Wk, Wv, Wfc
__device__ float g_s  [B_ * E_];                // column sums of X per batch
__device__ float g_bqs[B_ * E_];                // score^T bq (concatenated heads)
__device__ float g_b2 [B_ * E_];                // final fused bias
__device__ float g_p1 [4 * BH_ * HD_ * HD_];    // partial Wk^T G Wk
__device__ float g_p2 [4 * BH_ * HD_ * HD_];    // partial Wk^T G Wv
__device__ float g_score[BH_ * HD_ * HD_];      // softmax(solve(...))

// ---------------- helpers ---------------------------------------------------
__device__ __forceinline__ float tf32r(float x) {
    uint32_t u; asm("cvt.rna.tf32.f32 %0, %1;" : "=r"(u) : "f"(x));
    return __uint_as_float(u);
}
__device__ __forceinline__ void cp16(float* s, const float* g) {
    unsigned sa = (unsigned)__cvta_generic_to_shared(s);
    asm volatile("cp.async.cg.shared.global [%0], [%1], 16;" :: "r"(sa), "l"(g));
}
__device__ __forceinline__ void cp_commit() {
    asm volatile("cp.async.commit_group;");
}

// ---------------- elementwise tf32 rounding pass ---------------------------
__global__ void round4(const float* __restrict__ in, float* __restrict__ out, int n4) {
    int i = blockIdx.x * 256 + threadIdx.x;
    if (i >= n4) return;
    float4 v = reinterpret_cast<const float4*>(in)[i];
    v.x = tf32r(v.x); v.y = tf32r(v.y); v.z = tf32r(v.z); v.w = tf32r(v.w);
    reinterpret_cast<float4*>(out)[i] = v;
}

// ================= generic batched GEMM: C[z] = A[z] @ W[z]  (tf32 wmma) ===
// Operands MUST be tf32-prerounded (no in-kernel conversion).
#define BM 128
#define BN 128
#define BK 32
#define LDAS 40
#define LDBS 136
#define GEMM_SMEM ((2 * BM * LDAS + 2 * BK * LDBS) * sizeof(float))

__global__ __launch_bounds__(256, 2)
void gemm_tf32(const float* __restrict__ A, const float* __restrict__ W,
               float* __restrict__ C, int M, int N, int K,
               long long sA, long long sB, long long sC, int round_out) {
    A += (long long)blockIdx.z * sA;
    W += (long long)blockIdx.z * sB;
    C += (long long)blockIdx.z * sC;
    extern __shared__ float sm[];
    float* As = sm;
    float* Bs = sm + 2 * BM * LDAS;
    const int tid = threadIdx.x;
    const int bm = blockIdx.y, bn = blockIdx.x;
    const int wid = tid >> 5;
    const int wr = wid >> 1, wc = wid & 1;  // 4x2 warp grid; warp tile 32x64

    wmma::fragment<wmma::accumulator, 16, 16, 8, float> acc[2][4];
#pragma unroll
    for (int i = 0; i < 2; i++)
#pragma unroll
        for (int j = 0; j < 4; j++) wmma::fill_fragment(acc[i][j], 0.0f);

    const int KT = K / BK;

    auto load_tile = [&](int kt, int buf) {
        const float* Ag = A + (size_t)bm * BM * K + (size_t)kt * BK;
        float* Asb = As + buf * BM * LDAS;
#pragma unroll
        for (int p = 0; p < 4; p++) {
            int id = tid + p * 256;
            int r = id >> 3, c = (id & 7) << 2;
            cp16(Asb + r * LDAS + c, Ag + (size_t)r * K + c);
        }
        const float* Wg = W + (size_t)kt * BK * N + (size_t)bn * BN;
        float* Bsb = Bs + buf * BK * LDBS;
#pragma unroll
        for (int p = 0; p < 4; p++) {
            int id = tid + p * 256;
            int r = id >> 5, c = (id & 31) << 2;
            cp16(Bsb + r * LDBS + c, Wg + (size_t)r * N + c);
        }
    };

    load_tile(0, 0);
    cp_commit();

    for (int kt = 0; kt < KT; kt++) {
        int cur = kt & 1;
        if (kt + 1 < KT) {
            load_tile(kt + 1, cur ^ 1);
            cp_commit();
            asm volatile("cp.async.wait_group 1;");
        } else {
            asm volatile("cp.async.wait_group 0;");
        }
        __syncthreads();
        const float* Asb = As + cur * BM * LDAS;
        const float* Bsb = Bs + cur * BK * LDBS;
#pragma unroll
        for (int ks = 0; ks < BK; ks += 8) {
            wmma::fragment<wmma::matrix_a, 16, 16, 8, wmma::precision::tf32, wmma::row_major> af[2];
            wmma::fragment<wmma::matrix_b, 16, 16, 8, wmma::precision::tf32, wmma::row_major> bf[4];
#pragma unroll
            for (int i = 0; i < 2; i++)
                wmma::load_matrix_sync(af[i], Asb + (wr * 32 + i * 16) * LDAS + ks, LDAS);
#pragma unroll
            for (int j = 0; j < 4; j++)
                wmma::load_matrix_sync(bf[j], Bsb + ks * LDBS + wc * 64 + j * 16, LDBS);
#pragma unroll
            for (int i = 0; i < 2; i++)
#pragma unroll
                for (int j = 0; j < 4; j++)
                    wmma::mma_sync(acc[i][j], af[i], bf[j], acc[i][j]);
        }
        __syncthreads();
    }

    if (round_out) {
#pragma unroll
        for (int i = 0; i < 2; i++)
#pragma unroll
            for (int j = 0; j < 4; j++)
#pragma unroll
                for (int e = 0; e < acc[i][j].num_elements; e++)
                    acc[i][j].x[e] = tf32r(acc[i][j].x[e]);
    }

    float* Cg = C + (size_t)(bm * BM + wr * 32) * N + (size_t)bn * BN + wc * 64;
#pragma unroll
    for (int i = 0; i < 2; i++)
#pragma unroll
        for (int j = 0; j < 4; j++)
            wmma::store_matrix_sync(Cg + (size_t)i * 16 * N + j * 16, acc[i][j], N,
                                    wmma::mem_row_major);
}

// ---------------- column sums: s[b][e] = sum_m x[b][m][e] -------------------
__global__ void colsum(const float* __restrict__ x) {
    __shared__ float red[256];
    const int tid = threadIdx.x;
    const int tx = tid & 31, ty = tid >> 5;
    const int e = blockIdx.x * 32 + tx;
    const int b = blockIdx.y;
    const float* xb = x + (size_t)b * S_ * E_ + e;
    float acc = 0.f;
    for (int m = ty; m < S_; m += 8) acc += xb[(size_t)m * E_];
    red[ty * 32 + tx] = acc;
    __syncthreads();
    if (ty == 0) {
        float t = 0.f;
#pragma unroll
        for (int i = 0; i < 8; i++) t += red[i * 32 + tx];
        g_s[b * E_ + e] = t;
    }
}

// ------- G = Xr^T Xr (upper tiles; transposed store fills lower) -----------
#define SYRK_SMEM (2 * 32 * 136 * sizeof(float))
__global__ __launch_bounds__(256, 2)
void syrk_xtx(const float* __restrict__ x) {
    int rem = blockIdx.x, i = 0;
    while (rem >= 16 - i) { rem -= (16 - i); i++; }
    const int j = i + rem;
    const int b = blockIdx.y;
    extern __shared__ float sm[];
    float* As = sm;
    float* Bs = sm + 32 * 136;
    const int tid = threadIdx.x;
    const int wid = tid >> 5, wr = wid >> 1, wc = wid & 1;

    const float* ai = x + (size_t)b * S_ * E_ + i * 128;
    const float* bj = x + (size_t)b * S_ * E_ + j * 128;

    wmma::fragment<wmma::accumulator, 16, 16, 8, float> acc[2][4];
#pragma unroll
    for (int p = 0; p < 2; p++)
#pragma unroll
        for (int q = 0; q < 4; q++) wmma::fill_fragment(acc[p][q], 0.0f);

    for (int ss = 0; ss < S_; ss += 32) {
        __syncthreads();
#pragma unroll
        for (int p = 0; p < 4; p++) {
            int id = tid + p * 256;
            int r = id >> 5, c = (id & 31) << 2;
            *reinterpret_cast<float4*>(As + r * 136 + c) =
                *reinterpret_cast<const float4*>(ai + (size_t)(ss + r) * E_ + c);
            *reinterpret_cast<float4*>(Bs + r * 136 + c) =
                *reinterpret_cast<const float4*>(bj + (size_t)(ss + r) * E_ + c);
        }
        __syncthreads();
#pragma unroll
        for (int ks = 0; ks < 32; ks += 8) {
            wmma::fragment<wmma::matrix_a, 16, 16, 8, wmma::precision::tf32, wmma::col_major> af[2];
#pragma unroll
            for (int p = 0; p < 2; p++)
                wmma::load_matrix_sync(af[p], As + ks * 136 + wr * 32 + p * 16, 136);
#pragma unroll
            for (int q = 0; q < 4; q++) {
                wmma::fragment<wmma::matrix_b, 16, 16, 8, wmma::precision::tf32, wmma::row_major> bf;
                wmma::load_matrix_sync(bf, Bs + ks * 136 + wc * 64 + q * 16, 136);
                wmma::mma_sync(acc[0][q], af[0], bf, acc[0][q]);
                wmma::mma_sync(acc[1][q], af[1], bf, acc[1][q]);
            }
        }
    }

    float* Gb = g_G + (size_t)b * E_ * E_;
#pragma unroll
    for (int p = 0; p < 2; p++)
#pragma unroll
        for (int q = 0; q < 4; q++) {
#pragma unroll
            for (int e = 0; e < acc[p][q].num_elements; e++)
                acc[p][q].x[e] = tf32r(acc[p][q].x[e]);
            int rr = wr * 32 + p * 16, cc = wc * 64 + q * 16;
            wmma::store_matrix_sync(Gb + (size_t)(i * 128 + rr) * E_ + j * 128 + cc,
                                    acc[p][q], E_, wmma::mem_row_major);
            if (i != j)
                wmma::store_matrix_sync(Gb + (size_t)(j * 128 + cc) * E_ + i * 128 + rr,
                                        acc[p][q], E_, wmma::mem_col_major);
        }
}

// --------- per-head raw mats: p1 = Wk_h^T Yk[:,h], p2 = Wk_h^T Yv[:,h] -----
// Wkr (rounded), yk/yv (rounded at producer) -> no conversions here.
#define HB_SMEM (3 * 32 * 136 * sizeof(float))
__global__ void head_build(const float* __restrict__ Wkr) {
    const int bh = blockIdx.x, chunk = blockIdx.y;
    const int b = bh >> 4, h = bh & 15;
    extern __shared__ float sm[];
    float* Ws  = sm;
    float* Yks = sm + 32 * 136;
    float* Yvs = sm + 2 * 32 * 136;
    const int tid = threadIdx.x;
    const int wid = tid >> 5, wr = wid >> 1, wc = wid & 1;

    const float* wbase = Wkr + h * 128;
    const float* ykb = g_yk + (size_t)b * E_ * E_ + h * 128;
    const float* yvb = g_yv + (size_t)b * E_ * E_ + h * 128;
    const int k0 = chunk * 512;

    wmma::fragment<wmma::accumulator, 16, 16, 8, float> acck[2][4], accv[2][4];
#pragma unroll
    for (int p = 0; p < 2; p++)
#pragma unroll
        for (int q = 0; q < 4; q++) {
            wmma::fill_fragment(acck[p][q], 0.0f);
            wmma::fill_fragment(accv[p][q], 0.0f);
        }

    for (int ss = 0; ss < 512; ss += 32) {
        __syncthreads();
#pragma unroll
        for (int p = 0; p < 4; p++) {
            int id = tid + p * 256;
            int r = id >> 5, c = (id & 31) << 2;
            size_t row = (size_t)(k0 + ss + r) * E_;
            *reinterpret_cast<float4*>(Ws  + r * 136 + c) =
                *reinterpret_cast<const float4*>(wbase + row + c);
            *reinterpret_cast<float4*>(Yks + r * 136 + c) =
                *reinterpret_cast<const float4*>(ykb + row + c);
            *reinterpret_cast<float4*>(Yvs + r * 136 + c) =
                *reinterpret_cast<const float4*>(yvb + row + c);
        }
        __syncthreads();
#pragma unroll
        for (int ks = 0; ks < 32; ks += 8) {
            wmma::fragment<wmma::matrix_a, 16, 16, 8, wmma::precision::tf32, wmma::col_major> af[2];
#pragma unroll
            for (int p = 0; p < 2; p++)
                wmma::load_matrix_sync(af[p], Ws + ks * 136 + wr * 32 + p * 16, 136);
#pragma unroll
            for (int q = 0; q < 4; q++) {
                wmma::fragment<wmma::matrix_b, 16, 16, 8, wmma::precision::tf32, wmma::row_major> bf;
                wmma::load_matrix_sync(bf, Yks + ks * 136 + wc * 64 + q * 16, 136);
                wmma::mma_sync(acck[0][q], af[0], bf, acck[0][q]);
                wmma::mma_sync(acck[1][q], af[1], bf, acck[1][q]);
                wmma::load_matrix_sync(bf, Yvs + ks * 136 + wc * 64 + q * 16, 136);
                wmma::mma_sync(accv[0][q], af[0], bf, accv[0][q]);
                wmma::mma_sync(accv[1][q], af[1], bf, accv[1][q]);
            }
        }
    }
    float* p1 = g_p1 + ((size_t)chunk * BH_ + bh) * (HD_ * HD_);
    float* p2 = g_p2 + ((size_t)chunk * BH_ + bh) * (HD_ * HD_);
#pragma unroll
    for (int p = 0; p < 2; p++)
#pragma unroll
        for (int q = 0; q < 4; q++) {
            wmma::store_matrix_sync(p1 + (wr * 32 + p * 16) * HD_ + wc * 64 + q * 16,
                                    acck[p][q], HD_, wmma::mem_row_major);
            wmma::store_matrix_sync(p2 + (wr * 32 + p * 16) * HD_ + wc * 64 + q * 16,
                                    accv[p][q], HD_, wmma::mem_row_major);
        }
}

// -------- solver: bias rank-1s + alpha*I, Cholesky solve, softmax, bqs -----
#define SOLVER_SMEM ((2 * 128 * 129 + 6 * 128 + 512) * sizeof(float))
__global__ void solver(const float* __restrict__ alpha,
                       const float* __restrict__ Wk, const float* __restrict__ Wv,
                       const float* __restrict__ bk, const float* __restrict__ bv,
                       const float* __restrict__ bq) {
    const int bh = blockIdx.x;
    const int b = bh >> 4, h = bh & 15;
    const int tid = threadIdx.x;
    extern __shared__ float sm[];
    float* Am  = sm;
    float* Bm  = Am + 128 * 129;
    float* uK  = Bm + 128 * 129;
    float* uV  = uK + 128;
    float* bks = uV + 128;
    float* bvs = bks + 128;
    float* bqv = bvs + 128;
    float* sinv = bqv + 128;
    float* uKp = sinv + 128;   // [2][128]
    float* uVp = uKp + 256;    // [2][128]

    {
        const int c = tid & 127, half = tid >> 7;
        const float* sb = g_s + b * E_;
        const float* pk = Wk + h * 128 + c;
        const float* pv = Wv + h * 128 + c;
        float ak = 0.f, av = 0.f;
#pragma unroll 4
        for (int k = half * 1024; k < half * 1024 + 1024; k++) {
            float sv = sb[k];
            ak += pk[(size_t)k * E_] * sv;
            av += pv[(size_t)k * E_] * sv;
        }
        uKp[half * 128 + c] = ak;
        uVp[half * 128 + c] = av;
        if (tid < 128) {
            bks[tid] = bk[h * 128 + tid];
            bvs[tid] = bv[h * 128 + tid];
            bqv[tid] = bq[h * 128 + tid];
        }
    }
    __syncthreads();
    if (tid < 128) {
        uK[tid] = uKp[tid] + uKp[128 + tid];
        uV[tid] = uVp[tid] + uVp[128 + tid];
    }
    __syncthreads();

    const float a = alpha[0];
    for (int i = tid; i < HD_ * HD_; i += 256) {
        int r = i >> 7, c = i & 127;
        float s1 = 0.f, s2 = 0.f;
#pragma unroll
        for (int ch = 0; ch < 4; ch++) {
            s1 += g_p1[((size_t)ch * BH_ + bh) * (HD_ * HD_) + i];
            s2 += g_p2[((size_t)ch * BH_ + bh) * (HD_ * HD_) + i];
        }
        Am[r * 129 + c] = s1 + uK[r] * bks[c] + bks[r] * uK[c]
                          + (float)S_ * bks[r] * bks[c] + ((r == c) ? a : 0.f);
        Bm[r * 129 + c] = s2 + uK[r] * bvs[c] + bks[r] * uV[c]
                          + (float)S_ * bks[r] * bvs[c];
    }
    __syncthreads();

    for (int j = 0; j < HD_; j++) {
        if (tid == 0) Am[j * 129 + j] = sqrtf(Am[j * 129 + j]);
        __syncthreads();
        float dinv = 1.0f / Am[j * 129 + j];
        int n = 127 - j;
        for (int i = tid; i < n; i += 256) Am[(j + 1 + i) * 129 + j] *= dinv;
        __syncthreads();
        int tot = n * n;
        for (int t = tid; t < tot; t += 256) {
            int ri = j + 1 + t / n, ci = j + 1 + t % n;
            Am[ri * 129 + ci] -= Am[ri * 129 + j] * Am[ci * 129 + j];
        }
        __syncthreads();
    }

    if (tid < 128) {
        const int c = tid;
        for (int i = 0; i < 128; i++) {
            float t = Bm[i * 129 + c];
            for (int j2 = 0; j2 < i; j2++) t -= Am[i * 129 + j2] * Bm[j2 * 129 + c];
            Bm[i * 129 + c] = t / Am[i * 129 + i];
        }
        for (int i = 127; i >= 0; i--) {
            float t = Bm[i * 129 + c];
            for (int j2 = i + 1; j2 < 128; j2++) t -= Am[j2 * 129 + i] * Bm[j2 * 129 + c];
            Bm[i * 129 + c] = t / Am[i * 129 + i];
        }
    }
    __syncthreads();

    if (tid < 128) {
        const int r = tid;
        float m = -1e30f;
        for (int c = 0; c < 128; c++) m = fmaxf(m, Bm[r * 129 + c]);
        float s = 0.f;
        for (int c = 0; c < 128; c++) {
            float e = expf(Bm[r * 129 + c] - m);
            Bm[r * 129 + c] = e;
            s += e;
        }
        float inv = 1.0f / s;
        sinv[r] = inv;
        for (int c = 0; c < 128; c++)
            g_score[(size_t)bh * (HD_ * HD_) + r * HD_ + c] = Bm[r * 129 + c] * inv;
    }
    __syncthreads();

    if (tid < 128) {
        const int c = tid;
        float acc = 0.f;
        for (int r = 0; r < 128; r++) acc += bqv[r] * Bm[r * 129 + c] * sinv[r];
        g_bqs[b * E_ + h * 128 + c] = acc;
    }
}

// ------ Wqs[:, hblk] = Wq[:, hblk] @ score_bh  (fp32 SIMT, rounded store) --
#define WQS_SMEM (128 * 132 * sizeof(float))
__global__ void wqs_kernel(const float* __restrict__ Wq) {
    const int bx = blockIdx.x, h = blockIdx.y, b = blockIdx.z;
    extern __shared__ float sc[];  // [128][132]
    const int tid = threadIdx.x;
    const float* sg = g_score + (size_t)(b * NH_ + h) * (HD_ * HD_);
    for (int i = tid; i < 128 * 128; i += 256) {
        int r = i >> 7, c = i & 127;
        sc[r * 132 + c] = sg[i];
    }
    __syncthreads();

    const int pr = tid >> 4, pc = tid & 15;  // 16x16 patches of 8x8
    const float* wrow = Wq + (size_t)(bx * 128 + pr * 8) * E_ + h * 128;
    float acc[8][8];
#pragma unroll
    for (int i = 0; i < 8; i++)
#pragma unroll
        for (int j = 0; j < 8; j++) acc[i][j] = 0.f;

    for (int k = 0; k < 128; k++) {
        float w8[8];
#pragma unroll
        for (int i = 0; i < 8; i++) w8[i] = wrow[(size_t)i * E_ + k];
        float4 s0 = *reinterpret_cast<const float4*>(&sc[k * 132 + pc * 8]);
        float4 s1 = *reinterpret_cast<const float4*>(&sc[k * 132 + pc * 8 + 4]);
        float s8[8] = {s0.x, s0.y, s0.z, s0.w, s1.x, s1.y, s1.z, s1.w};
#pragma unroll
        for (int i = 0; i < 8; i++)
#pragma unroll
            for (int j = 0; j < 8; j++) acc[i][j] += w8[i] * s8[j];
    }

    float* og = g_wqs + (size_t)b * E_ * E_ + (size_t)(bx * 128 + pr * 8) * E_ + h * 128 + pc * 8;
#pragma unroll
    for (int i = 0; i < 8; i++) {
        *reinterpret_cast<float4*>(og + (size_t)i * E_) =
            make_float4(tf32r(acc[i][0]), tf32r(acc[i][1]), tf32r(acc[i][2]), tf32r(acc[i][3]));
        *reinterpret_cast<float4*>(og + (size_t)i * E_ + 4) =
            make_float4(tf32r(acc[i][4]), tf32r(acc[i][5]), tf32r(acc[i][6]), tf32r(acc[i][7]));
    }
}

// ------ b2[b][n] = sum_k bqs[b][k] * Wfc[k][n] + bfc[n] --------------------
__global__ void b2_build(const float* __restrict__ Wfc, const float* __restrict__ bfc) {
    const int n = blockIdx.x * 256 + threadIdx.x;
    const int b = blockIdx.y;
    const float* bqs = g_bqs + b * E_;
    float acc = bfc[n];
    for (int k = 0; k < E_; k++) acc += bqs[k] * Wfc[(size_t)k * E_ + n];
    g_b2[b * E_ + n] = acc;
}

// ------ out += b2 (per batch) ----------------------------------------------
__global__ void bias_add_b2(float* __restrict__ C) {
    int i = blockIdx.x * 256 + threadIdx.x;
    int batch = i >> 21;            // S_*E_/4 = 2^21 float4 per batch
    int nb = i & (E_ / 4 - 1);
    float4 c = reinterpret_cast<float4*>(C)[i];
    float4 bb = reinterpret_cast<const float4*>(g_b2 + batch * E_)[nb];
    c.x += bb.x; c.y += bb.y; c.z += bb.z; c.w += bb.w;
    reinterpret_cast<float4*>(C)[i] = c;
}

// ---------------- host entry ------------------------------------------------
extern "C" void kernel_launch(void* const* d_in, const int* in_sizes, int n_in,
                              void* d_out, int out_size) {
    (void)in_sizes; (void)n_in; (void)out_size;
    const float* x     = (const float*)d_in[0];
    const float* alpha = (const float*)d_in[1];
    const float* Wq    = (const float*)d_in[2];
    const float* bq    = (const float*)d_in[3];
    const float* Wk    = (const float*)d_in[4];
    const float* bk    = (const float*)d_in[5];
    const float* Wv    = (const float*)d_in[6];
    const float* bv    = (const float*)d_in[7];
    const float* Wfc   = (const float*)d_in[8];
    const float* bfc   = (const float*)d_in[9];
    float* out = (float*)d_out;

    float *G, *yk, *yv, *wqs, *w2, *xr, *wr;
    cudaGetSymbolAddress((void**)&G,   g_G);
    cudaGetSymbolAddress((void**)&yk,  g_yk);
    cudaGetSymbolAddress((void**)&yv,  g_yv);
    cudaGetSymbolAddress((void**)&wqs, g_wqs);
    cudaGetSymbolAddress((void**)&w2,  g_w2);
    cudaGetSymbolAddress((void**)&xr,  g_xr);
    cudaGetSymbolAddress((void**)&wr,  g_wr);

    cudaFuncSetAttribute(gemm_tf32, cudaFuncAttributeMaxDynamicSharedMemorySize, GEMM_SMEM);
    cudaFuncSetAttribute(syrk_xtx, cudaFuncAttributeMaxDynamicSharedMemorySize, SYRK_SMEM);
    cudaFuncSetAttribute(head_build, cudaFuncAttributeMaxDynamicSharedMemorySize, HB_SMEM);
    cudaFuncSetAttribute(solver, cudaFuncAttributeMaxDynamicSharedMemorySize, SOLVER_SMEM);
    cudaFuncSetAttribute(wqs_kernel, cudaFuncAttributeMaxDynamicSharedMemorySize, WQS_SMEM);

    const long long EE = (long long)E_ * E_;
    const long long SE = (long long)S_ * E_;
    const int nx4 = M_TOT * E_ / 4;
    const int nw4 = E_ * E_ / 4;
    float* wkr = wr + 0 * EE;
    float* wvr = wr + 1 * EE;
    float* wfr = wr + 2 * EE;

    // pre-round all tensor operands (numerically identical to in-kernel cvt)
    round4<<<nx4 / 256, 256>>>(x, xr, nx4);
    round4<<<nw4 / 256, 256>>>(Wk, wkr, nw4);
    round4<<<nw4 / 256, 256>>>(Wv, wvr, nw4);
    round4<<<nw4 / 256, 256>>>(Wfc, wfr, nw4);

    // K/V side via G = X^T X
    colsum<<<dim3(E_ / 32, B_), 256>>>(x);
    syrk_xtx<<<dim3(136, B_), 256, SYRK_SMEM>>>(xr);
    gemm_tf32<<<dim3(16, 16, B_), 256, GEMM_SMEM>>>(G, wkr, yk, E_, E_, E_, EE, 0, EE, 1);
    gemm_tf32<<<dim3(16, 16, B_), 256, GEMM_SMEM>>>(G, wvr, yv, E_, E_, E_, EE, 0, EE, 1);
    head_build<<<dim3(BH_, 4), 256, HB_SMEM>>>(wkr);
    solver<<<BH_, 256, SOLVER_SMEM>>>(alpha, Wk, Wv, bk, bv, bq);

    // Q side collapsed: out = X @ (Wq BD(score) Wfc) + b2
    wqs_kernel<<<dim3(16, NH_, B_), 256, WQS_SMEM>>>(Wq);
    b2_build<<<dim3(E_ / 256, B_), 256>>>(Wfc, bfc);
    gemm_tf32<<<dim3(16, 16, B_), 256, GEMM_SMEM>>>(wqs, wfr, w2, E_, E_, E_, EE, 0, EE, 1);
    gemm_tf32<<<dim3(16, 32, B_), 256, GEMM_SMEM>>>(xr, w2, out, S_, E_, E_, SE, EE, SE, 0);
    bias_add_b2<<<(M_TOT * E_ / 4) / 256, 256>>>(out);
}

// round 12
// speedup vs baseline: 1.4425x; 1.0666x over previous
#include <cuda_runtime.h>
#include <mma.h>
#include <cstdint>

using namespace nvcuda;

// Problem constants
#define B_    4
#define S_    4096
#define E_    2048
#define NH_   16
#define HD_   128
#define M_TOT (B_ * S_)   // 16384
#define BH_   (B_ * NH_)  // 64

// ---------------- scratch (static device allocations; no cudaMalloc) -------
__device__ float g_G  [(size_t)B_ * E_ * E_];   // per-batch X^T X (tf32-rounded)
__device__ float g_yk [(size_t)B_ * E_ * E_];   // G @ Wk (rounded)
__device__ float g_yv [(size_t)B_ * E_ * E_];   // G @ Wv (rounded)
__device__ float g_wqs[(size_t)B_ * E_ * E_];   // Wq @ blockdiag(score) (rounded)
__device__ float g_w2 [(size_t)B_ * E_ * E_];   // Wqs @ Wfc (rounded)
__device__ float g_xr [(size_t)M_TOT * E_];     // tf32-rounded x
__device__ float g_wr [(size_t)3 * E_ * E_];    // rounded Wk, Wv, Wfc
__device__ float g_s  [B_ * E_];                // column sums of X per batch
__device__ float g_bqs[B_ * E_];                // score^T bq (concatenated heads)
__device__ float g_b2 [B_ * E_];                // final fused bias
__device__ float g_p1 [4 * BH_ * HD_ * HD_];    // partial Wk^T G Wk
__device__ float g_p2 [4 * BH_ * HD_ * HD_];    // partial Wk^T G Wv
__device__ float g_score[BH_ * HD_ * HD_];      // softmax(solve(...))

// ---------------- helpers ---------------------------------------------------
__device__ __forceinline__ float tf32r(float x) {
    uint32_t u; asm("cvt.rna.tf32.f32 %0, %1;" : "=r"(u) : "f"(x));
    return __uint_as_float(u);
}
__device__ __forceinline__ void cp16(float* s, const float* g) {
    unsigned sa = (unsigned)__cvta_generic_to_shared(s);
    asm volatile("cp.async.cg.shared.global [%0], [%1], 16;" :: "r"(sa), "l"(g));
}
__device__ __forceinline__ void cp_commit() {
    asm volatile("cp.async.commit_group;");
}

// ---------------- elementwise tf32 rounding pass ---------------------------
__global__ void round4(const float* __restrict__ in, float* __restrict__ out, int n4) {
    int i = blockIdx.x * 256 + threadIdx.x;
    if (i >= n4) return;
    float4 v = reinterpret_cast<const float4*>(in)[i];
    v.x = tf32r(v.x); v.y = tf32r(v.y); v.z = tf32r(v.z); v.w = tf32r(v.w);
    reinterpret_cast<float4*>(out)[i] = v;
}

// ============ GEMM v2: 128x256 block, 64x64 warp tile, 3-stage cp.async ====
// C[z] = A[z] @ Wsel[z]; dual-output mode: blocks with bn >= nbx use (Wb, Cb).
// All operands tf32-prerounded.
#define BM 128
#define BN 256
#define BK 32
#define NSTG 3
#define LDA 40                       // 32 + 8 pad (floats)
#define LDB 264                      // 256 + 8 pad (floats)
#define A_STG (BM * LDA)             // 5120 floats
#define B_STG (BK * LDB)             // 8448 floats
#define GEMM2_SMEM (NSTG * (A_STG + B_STG) * sizeof(float))  // 162816 B

__global__ __launch_bounds__(256, 1)
void gemm2(const float* __restrict__ A,
           const float* __restrict__ W, const float* __restrict__ Wb,
           float* __restrict__ C, float* __restrict__ Cb,
           int M, int N, int K,
           long long sA, long long sB, long long sC, int nbx, int round_out) {
    A += (long long)blockIdx.z * sA;
    int bn = blockIdx.x;
    const float* Wsel; float* Csel;
    if (bn >= nbx) { Wsel = Wb; Csel = Cb; bn -= nbx; }
    else           { Wsel = W;  Csel = C; }
    Wsel += (long long)blockIdx.z * sB;
    Csel += (long long)blockIdx.z * sC;

    extern __shared__ float sm[];
    float* As = sm;                   // NSTG stages of A
    float* Bs = sm + NSTG * A_STG;    // NSTG stages of B
    const int tid = threadIdx.x;
    const int bm = blockIdx.y;
    const int wid = tid >> 5;
    const int wr = wid >> 2, wc = wid & 3;   // 2x4 warp grid, warp tile 64x64

    wmma::fragment<wmma::accumulator, 16, 16, 8, float> acc[4][4];
#pragma unroll
    for (int i = 0; i < 4; i++)
#pragma unroll
        for (int j = 0; j < 4; j++) wmma::fill_fragment(acc[i][j], 0.0f);

    const int KT = K / BK;
    const float* Ab = A + (size_t)bm * BM * K;
    const float* Bb = Wsel + (size_t)bn * BN;

    auto load_stage = [&](int kt, int buf) {
        float* Asb = As + buf * A_STG;
        const float* Ag = Ab + kt * BK;
#pragma unroll
        for (int p = 0; p < 4; p++) {
            int id = tid + p * 256;
            int r = id >> 3, c = (id & 7) << 2;       // 128 rows x 8 float4
            cp16(Asb + r * LDA + c, Ag + (size_t)r * K + c);
        }
        float* Bsb = Bs + buf * B_STG;
        const float* Bg = Bb + (size_t)kt * BK * N;
#pragma unroll
        for (int p = 0; p < 8; p++) {
            int id = tid + p * 256;
            int r = id >> 6, c = (id & 63) << 2;      // 32 rows x 64 float4
            cp16(Bsb + r * LDB + c, Bg + (size_t)r * N + c);
        }
        cp_commit();
    };

    load_stage(0, 0);
    load_stage(1, 1);

    for (int kt = 0; kt < KT; kt++) {
        if (kt + 1 < KT) asm volatile("cp.async.wait_group 1;");
        else             asm volatile("cp.async.wait_group 0;");
        __syncthreads();
        const int buf = kt % NSTG;
        const float* Asb = As + buf * A_STG;
        const float* Bsb = Bs + buf * B_STG;
#pragma unroll
        for (int ks = 0; ks < BK; ks += 8) {
            wmma::fragment<wmma::matrix_a, 16, 16, 8, wmma::precision::tf32, wmma::row_major> af[4];
            wmma::fragment<wmma::matrix_b, 16, 16, 8, wmma::precision::tf32, wmma::row_major> bf[4];
#pragma unroll
            for (int i = 0; i < 4; i++)
                wmma::load_matrix_sync(af[i], Asb + (wr * 64 + i * 16) * LDA + ks, LDA);
#pragma unroll
            for (int j = 0; j < 4; j++)
                wmma::load_matrix_sync(bf[j], Bsb + ks * LDB + wc * 64 + j * 16, LDB);
#pragma unroll
            for (int i = 0; i < 4; i++)
#pragma unroll
                for (int j = 0; j < 4; j++)
                    wmma::mma_sync(acc[i][j], af[i], bf[j], acc[i][j]);
        }
        if (kt + 2 < KT) load_stage(kt + 2, (kt + 2) % NSTG);
        __syncthreads();
    }

    if (round_out) {
#pragma unroll
        for (int i = 0; i < 4; i++)
#pragma unroll
            for (int j = 0; j < 4; j++)
#pragma unroll
                for (int e = 0; e < acc[i][j].num_elements; e++)
                    acc[i][j].x[e] = tf32r(acc[i][j].x[e]);
    }

    float* Cg = Csel + (size_t)(bm * BM + wr * 64) * N + (size_t)bn * BN + wc * 64;
#pragma unroll
    for (int i = 0; i < 4; i++)
#pragma unroll
        for (int j = 0; j < 4; j++)
            wmma::store_matrix_sync(Cg + (size_t)i * 16 * N + j * 16, acc[i][j], N,
                                    wmma::mem_row_major);
}

// ---------------- column sums: s[b][e] = sum_m x[b][m][e] -------------------
__global__ void colsum(const float* __restrict__ x) {
    __shared__ float red[256];
    const int tid = threadIdx.x;
    const int tx = tid & 31, ty = tid >> 5;
    const int e = blockIdx.x * 32 + tx;
    const int b = blockIdx.y;
    const float* xb = x + (size_t)b * S_ * E_ + e;
    float acc = 0.f;
    for (int m = ty; m < S_; m += 8) acc += xb[(size_t)m * E_];
    red[ty * 32 + tx] = acc;
    __syncthreads();
    if (ty == 0) {
        float t = 0.f;
#pragma unroll
        for (int i = 0; i < 8; i++) t += red[i * 32 + tx];
        g_s[b * E_ + e] = t;
    }
}

// ------- G = Xr^T Xr (upper tiles; transposed store fills lower) -----------
// 2-stage cp.async pipeline.
#define SY_STG (32 * 136)
#define SYRK_SMEM (2 * 2 * SY_STG * sizeof(float))
__global__ __launch_bounds__(256, 2)
void syrk_xtx(const float* __restrict__ x) {
    int rem = blockIdx.x, i = 0;
    while (rem >= 16 - i) { rem -= (16 - i); i++; }
    const int j = i + rem;
    const int b = blockIdx.y;
    extern __shared__ float sm[];
    float* As = sm;                      // 2 stages
    float* Bs = sm + 2 * SY_STG;
    const int tid = threadIdx.x;
    const int wid = tid >> 5, wr = wid >> 1, wc = wid & 1;

    const float* ai = x + (size_t)b * S_ * E_ + i * 128;
    const float* bj = x + (size_t)b * S_ * E_ + j * 128;

    wmma::fragment<wmma::accumulator, 16, 16, 8, float> acc[2][4];
#pragma unroll
    for (int p = 0; p < 2; p++)
#pragma unroll
        for (int q = 0; q < 4; q++) wmma::fill_fragment(acc[p][q], 0.0f);

    auto load_stage = [&](int it, int buf) {
        const int ss = it * 32;
#pragma unroll
        for (int p = 0; p < 4; p++) {
            int id = tid + p * 256;
            int r = id >> 5, c = (id & 31) << 2;
            cp16(As + buf * SY_STG + r * 136 + c, ai + (size_t)(ss + r) * E_ + c);
            cp16(Bs + buf * SY_STG + r * 136 + c, bj + (size_t)(ss + r) * E_ + c);
        }
        cp_commit();
    };

    const int IT = S_ / 32;   // 128
    load_stage(0, 0);
    for (int it = 0; it < IT; it++) {
        if (it + 1 < IT) { load_stage(it + 1, (it + 1) & 1);
                           asm volatile("cp.async.wait_group 1;"); }
        else             { asm volatile("cp.async.wait_group 0;"); }
        __syncthreads();
        const float* Asb = As + (it & 1) * SY_STG;
        const float* Bsb = Bs + (it & 1) * SY_STG;
#pragma unroll
        for (int ks = 0; ks < 32; ks += 8) {
            wmma::fragment<wmma::matrix_a, 16, 16, 8, wmma::precision::tf32, wmma::col_major> af[2];
#pragma unroll
            for (int p = 0; p < 2; p++)
                wmma::load_matrix_sync(af[p], Asb + ks * 136 + wr * 32 + p * 16, 136);
#pragma unroll
            for (int q = 0; q < 4; q++) {
                wmma::fragment<wmma::matrix_b, 16, 16, 8, wmma::precision::tf32, wmma::row_major> bf;
                wmma::load_matrix_sync(bf, Bsb + ks * 136 + wc * 64 + q * 16, 136);
                wmma::mma_sync(acc[0][q], af[0], bf, acc[0][q]);
                wmma::mma_sync(acc[1][q], af[1], bf, acc[1][q]);
            }
        }
        __syncthreads();
    }

    float* Gb = g_G + (size_t)b * E_ * E_;
#pragma unroll
    for (int p = 0; p < 2; p++)
#pragma unroll
        for (int q = 0; q < 4; q++) {
#pragma unroll
            for (int e = 0; e < acc[p][q].num_elements; e++)
                acc[p][q].x[e] = tf32r(acc[p][q].x[e]);
            int rr = wr * 32 + p * 16, cc = wc * 64 + q * 16;
            wmma::store_matrix_sync(Gb + (size_t)(i * 128 + rr) * E_ + j * 128 + cc,
                                    acc[p][q], E_, wmma::mem_row_major);
            if (i != j)
                wmma::store_matrix_sync(Gb + (size_t)(j * 128 + cc) * E_ + i * 128 + rr,
                                        acc[p][q], E_, wmma::mem_col_major);
        }
}

// --------- per-head raw mats: p1 = Wk_h^T Yk[:,h], p2 = Wk_h^T Yv[:,h] -----
// 2-stage cp.async pipeline.
#define HB_STG (3 * 32 * 136)
#define HB_SMEM (2 * HB_STG * sizeof(float))
__global__ void head_build(const float* __restrict__ Wkr) {
    const int bh = blockIdx.x, chunk = blockIdx.y;
    const int b = bh >> 4, h = bh & 15;
    extern __shared__ float sm[];
    const int tid = threadIdx.x;
    const int wid = tid >> 5, wr = wid >> 1, wc = wid & 1;

    const float* wbase = Wkr + h * 128;
    const float* ykb = g_yk + (size_t)b * E_ * E_ + h * 128;
    const float* yvb = g_yv + (size_t)b * E_ * E_ + h * 128;
    const int k0 = chunk * 512;

    wmma::fragment<wmma::accumulator, 16, 16, 8, float> acck[2][4], accv[2][4];
#pragma unroll
    for (int p = 0; p < 2; p++)
#pragma unroll
        for (int q = 0; q < 4; q++) {
            wmma::fill_fragment(acck[p][q], 0.0f);
            wmma::fill_fragment(accv[p][q], 0.0f);
        }

    auto load_stage = [&](int it, int buf) {
        float* base = sm + buf * HB_STG;
        const int ss = k0 + it * 32;
#pragma unroll
        for (int p = 0; p < 4; p++) {
            int id = tid + p * 256;
            int r = id >> 5, c = (id & 31) << 2;
            size_t row = (size_t)(ss + r) * E_;
            cp16(base + r * 136 + c,        wbase + row + c);
            cp16(base + 4352 + r * 136 + c, ykb + row + c);
            cp16(base + 8704 + r * 136 + c, yvb + row + c);
        }
        cp_commit();
    };

    const int IT = 16;  // 512 / 32
    load_stage(0, 0);
    for (int it = 0; it < IT; it++) {
        if (it + 1 < IT) { load_stage(it + 1, (it + 1) & 1);
                           asm volatile("cp.async.wait_group 1;"); }
        else             { asm volatile("cp.async.wait_group 0;"); }
        __syncthreads();
        const float* base = sm + (it & 1) * HB_STG;
        const float* Ws = base;
        const float* Yks = base + 4352;
        const float* Yvs = base + 8704;
#pragma unroll
        for (int ks = 0; ks < 32; ks += 8) {
            wmma::fragment<wmma::matrix_a, 16, 16, 8, wmma::precision::tf32, wmma::col_major> af[2];
#pragma unroll
            for (int p = 0; p < 2; p++)
                wmma::load_matrix_sync(af[p], Ws + ks * 136 + wr * 32 + p * 16, 136);
#pragma unroll
            for (int q = 0; q < 4; q++) {
                wmma::fragment<wmma::matrix_b, 16, 16, 8, wmma::precision::tf32, wmma::row_major> bf;
                wmma::load_matrix_sync(bf, Yks + ks * 136 + wc * 64 + q * 16, 136);
                wmma::mma_sync(acck[0][q], af[0], bf, acck[0][q]);
                wmma::mma_sync(acck[1][q], af[1], bf, acck[1][q]);
                wmma::load_matrix_sync(bf, Yvs + ks * 136 + wc * 64 + q * 16, 136);
                wmma::mma_sync(accv[0][q], af[0], bf, accv[0][q]);
                wmma::mma_sync(accv[1][q], af[1], bf, accv[1][q]);
            }
        }
        __syncthreads();
    }
    float* p1 = g_p1 + ((size_t)chunk * BH_ + bh) * (HD_ * HD_);
    float* p2 = g_p2 + ((size_t)chunk * BH_ + bh) * (HD_ * HD_);
#pragma unroll
    for (int p = 0; p < 2; p++)
#pragma unroll
        for (int q = 0; q < 4; q++) {
            wmma::store_matrix_sync(p1 + (wr * 32 + p * 16) * HD_ + wc * 64 + q * 16,
                                    acck[p][q], HD_, wmma::mem_row_major);
            wmma::store_matrix_sync(p2 + (wr * 32 + p * 16) * HD_ + wc * 64 + q * 16,
                                    accv[p][q], HD_, wmma::mem_row_major);
        }
}

// -------- solver: bias rank-1s + alpha*I, Cholesky solve, softmax, bqs -----
#define SOLVER_SMEM ((2 * 128 * 129 + 6 * 128 + 512) * sizeof(float))
__global__ void solver(const float* __restrict__ alpha,
                       const float* __restrict__ Wk, const float* __restrict__ Wv,
                       const float* __restrict__ bk, const float* __restrict__ bv,
                       const float* __restrict__ bq) {
    const int bh = blockIdx.x;
    const int b = bh >> 4, h = bh & 15;
    const int tid = threadIdx.x;
    extern __shared__ float sm[];
    float* Am  = sm;
    float* Bm  = Am + 128 * 129;
    float* uK  = Bm + 128 * 129;
    float* uV  = uK + 128;
    float* bks = uV + 128;
    float* bvs = bks + 128;
    float* bqv = bvs + 128;
    float* sinv = bqv + 128;
    float* uKp = sinv + 128;   // [2][128]
    float* uVp = uKp + 256;    // [2][128]

    {
        const int c = tid & 127, half = tid >> 7;
        const float* sb = g_s + b * E_;
        const float* pk = Wk + h * 128 + c;
        const float* pv = Wv + h * 128 + c;
        float ak = 0.f, av = 0.f;
#pragma unroll 8
        for (int k = half * 1024; k < half * 1024 + 1024; k++) {
            float sv = sb[k];
            ak += pk[(size_t)k * E_] * sv;
            av += pv[(size_t)k * E_] * sv;
        }
        uKp[half * 128 + c] = ak;
        uVp[half * 128 + c] = av;
        if (tid < 128) {
            bks[tid] = bk[h * 128 + tid];
            bvs[tid] = bv[h * 128 + tid];
            bqv[tid] = bq[h * 128 + tid];
        }
    }
    __syncthreads();
    if (tid < 128) {
        uK[tid] = uKp[tid] + uKp[128 + tid];
        uV[tid] = uVp[tid] + uVp[128 + tid];
    }
    __syncthreads();

    const float a = alpha[0];
    for (int i = tid; i < HD_ * HD_; i += 256) {
        int r = i >> 7, c = i & 127;
        float s1 = 0.f, s2 = 0.f;
#pragma unroll
        for (int ch = 0; ch < 4; ch++) {
            s1 += g_p1[((size_t)ch * BH_ + bh) * (HD_ * HD_) + i];
            s2 += g_p2[((size_t)ch * BH_ + bh) * (HD_ * HD_) + i];
        }
        Am[r * 129 + c] = s1 + uK[r] * bks[c] + bks[r] * uK[c]
                          + (float)S_ * bks[r] * bks[c] + ((r == c) ? a : 0.f);
        Bm[r * 129 + c] = s2 + uK[r] * bvs[c] + bks[r] * uV[c]
                          + (float)S_ * bks[r] * bvs[c];
    }
    __syncthreads();

    for (int j = 0; j < HD_; j++) {
        if (tid == 0) Am[j * 129 + j] = sqrtf(Am[j * 129 + j]);
        __syncthreads();
        float dinv = 1.0f / Am[j * 129 + j];
        int n = 127 - j;
        for (int i = tid; i < n; i += 256) Am[(j + 1 + i) * 129 + j] *= dinv;
        __syncthreads();
        int tot = n * n;
        for (int t = tid; t < tot; t += 256) {
            int ri = j + 1 + t / n, ci = j + 1 + t % n;
            Am[ri * 129 + ci] -= Am[ri * 129 + j] * Am[ci * 129 + j];
        }
        __syncthreads();
    }

    if (tid < 128) {
        const int c = tid;
        for (int i = 0; i < 128; i++) {
            float t = Bm[i * 129 + c];
            for (int j2 = 0; j2 < i; j2++) t -= Am[i * 129 + j2] * Bm[j2 * 129 + c];
            Bm[i * 129 + c] = t / Am[i * 129 + i];
        }
        for (int i = 127; i >= 0; i--) {
            float t = Bm[i * 129 + c];
            for (int j2 = i + 1; j2 < 128; j2++) t -= Am[j2 * 129 + i] * Bm[j2 * 129 + c];
            Bm[i * 129 + c] = t / Am[i * 129 + i];
        }
    }
    __syncthreads();

    if (tid < 128) {
        const int r = tid;
        float m = -1e30f;
        for (int c = 0; c < 128; c++) m = fmaxf(m, Bm[r * 129 + c]);
        float s = 0.f;
        for (int c = 0; c < 128; c++) {
            float e = expf(Bm[r * 129 + c] - m);
            Bm[r * 129 + c] = e;
            s += e;
        }
        float inv = 1.0f / s;
        sinv[r] = inv;
        for (int c = 0; c < 128; c++)
            g_score[(size_t)bh * (HD_ * HD_) + r * HD_ + c] = Bm[r * 129 + c] * inv;
    }
    __syncthreads();

    if (tid < 128) {
        const int c = tid;
        float acc = 0.f;
        for (int r = 0; r < 128; r++) acc += bqv[r] * Bm[r * 129 + c] * sinv[r];
        g_bqs[b * E_ + h * 128 + c] = acc;
    }
}

// ------ Wqs[:, hblk] = Wq[:, hblk] @ score_bh  (fp32 SIMT, rounded store) --
#define WQS_SMEM (128 * 132 * sizeof(float))
__global__ void wqs_kernel(const float* __restrict__ Wq) {
    const int bx = blockIdx.x, h = blockIdx.y, b = blockIdx.z;
    extern __shared__ float sc[];  // [128][132]
    const int tid = threadIdx.x;
    const float* sg = g_score + (size_t)(b * NH_ + h) * (HD_ * HD_);
    for (int i = tid; i < 128 * 128; i += 256) {
        int r = i >> 7, c = i & 127;
        sc[r * 132 + c] = sg[i];
    }
    __syncthreads();

    const int pr = tid >> 4, pc = tid & 15;  // 16x16 patches of 8x8
    const float* wrow = Wq + (size_t)(bx * 128 + pr * 8) * E_ + h * 128;
    float acc[8][8];
#pragma unroll
    for (int i = 0; i < 8; i++)
#pragma unroll
        for (int j = 0; j < 8; j++) acc[i][j] = 0.f;

    for (int k = 0; k < 128; k++) {
        float w8[8];
#pragma unroll
        for (int i = 0; i < 8; i++) w8[i] = wrow[(size_t)i * E_ + k];
        float4 s0 = *reinterpret_cast<const float4*>(&sc[k * 132 + pc * 8]);
        float4 s1 = *reinterpret_cast<const float4*>(&sc[k * 132 + pc * 8 + 4]);
        float s8[8] = {s0.x, s0.y, s0.z, s0.w, s1.x, s1.y, s1.z, s1.w};
#pragma unroll
        for (int i = 0; i < 8; i++)
#pragma unroll
            for (int j = 0; j < 8; j++) acc[i][j] += w8[i] * s8[j];
    }

    float* og = g_wqs + (size_t)b * E_ * E_ + (size_t)(bx * 128 + pr * 8) * E_ + h * 128 + pc * 8;
#pragma unroll
    for (int i = 0; i < 8; i++) {
        *reinterpret_cast<float4*>(og + (size_t)i * E_) =
            make_float4(tf32r(acc[i][0]), tf32r(acc[i][1]), tf32r(acc[i][2]), tf32r(acc[i][3]));
        *reinterpret_cast<float4*>(og + (size_t)i * E_ + 4) =
            make_float4(tf32r(acc[i][4]), tf32r(acc[i][5]), tf32r(acc[i][6]), tf32r(acc[i][7]));
    }
}

// ------ b2[b][n] = sum_k bqs[b][k] * Wfc[k][n] + bfc[n]  (k-parallel) ------
__global__ void b2_build(const float* __restrict__ Wfc, const float* __restrict__ bfc) {
    __shared__ float part[2][128];
    const int tid = threadIdx.x;
    const int nl = tid & 127, half = tid >> 7;
    const int n = blockIdx.x * 128 + nl;
    const int b = blockIdx.y;
    const float* bqs = g_bqs + b * E_;
    float acc = 0.f;
#pragma unroll 8
    for (int k = half * 1024; k < half * 1024 + 1024; k++)
        acc += bqs[k] * Wfc[(size_t)k * E_ + n];
    part[half][nl] = acc;
    __syncthreads();
    if (tid < 128)
        g_b2[b * E_ + n] = part[0][nl] + part[1][nl] + bfc[n];
}

// ------ out += b2 (per batch) ----------------------------------------------
__global__ void bias_add_b2(float* __restrict__ C) {
    int i = blockIdx.x * 256 + threadIdx.x;
    int batch = i >> 21;            // S_*E_/4 = 2^21 float4 per batch
    int nb = i & (E_ / 4 - 1);
    float4 c = reinterpret_cast<float4*>(C)[i];
    float4 bb = reinterpret_cast<const float4*>(g_b2 + batch * E_)[nb];
    c.x += bb.x; c.y += bb.y; c.z += bb.z; c.w += bb.w;
    reinterpret_cast<float4*>(C)[i] = c;
}

// ---------------- host entry ------------------------------------------------
extern "C" void kernel_launch(void* const* d_in, const int* in_sizes, int n_in,
                              void* d_out, int out_size) {
    (void)in_sizes; (void)n_in; (void)out_size;
    const float* x     = (const float*)d_in[0];
    const float* alpha = (const float*)d_in[1];
    const float* Wq    = (const float*)d_in[2];
    const float* bq    = (const float*)d_in[3];
    const float* Wk    = (const float*)d_in[4];
    const float* bk    = (const float*)d_in[5];
    const float* Wv    = (const float*)d_in[6];
    const float* bv    = (const float*)d_in[7];
    const float* Wfc   = (const float*)d_in[8];
    const float* bfc   = (const float*)d_in[9];
    float* out = (float*)d_out;

    float *G, *yk, *yv, *wqs, *w2, *xr, *wr;
    cudaGetSymbolAddress((void**)&G,   g_G);
    cudaGetSymbolAddress((void**)&yk,  g_yk);
    cudaGetSymbolAddress((void**)&yv,  g_yv);
    cudaGetSymbolAddress((void**)&wqs, g_wqs);
    cudaGetSymbolAddress((void**)&w2,  g_w2);
    cudaGetSymbolAddress((void**)&xr,  g_xr);
    cudaGetSymbolAddress((void**)&wr,  g_wr);

    cudaFuncSetAttribute(gemm2, cudaFuncAttributeMaxDynamicSharedMemorySize, GEMM2_SMEM);
    cudaFuncSetAttribute(syrk_xtx, cudaFuncAttributeMaxDynamicSharedMemorySize, SYRK_SMEM);
    cudaFuncSetAttribute(head_build, cudaFuncAttributeMaxDynamicSharedMemorySize, HB_SMEM);
    cudaFuncSetAttribute(solver, cudaFuncAttributeMaxDynamicSharedMemorySize, SOLVER_SMEM);
    cudaFuncSetAttribute(wqs_kernel, cudaFuncAttributeMaxDynamicSharedMemorySize, WQS_SMEM);

    const long long EE = (long long)E_ * E_;
    const long long SE = (long long)S_ * E_;
    const int nx4 = M_TOT * E_ / 4;
    const int nw4 = E_ * E_ / 4;
    float* wkr = wr + 0 * EE;
    float* wvr = wr + 1 * EE;
    float* wfr = wr + 2 * EE;

    // pre-round all tensor operands (numerically identical to in-kernel cvt)
    round4<<<nx4 / 256, 256>>>(x, xr, nx4);
    round4<<<nw4 / 256, 256>>>(Wk, wkr, nw4);
    round4<<<nw4 / 256, 256>>>(Wv, wvr, nw4);
    round4<<<nw4 / 256, 256>>>(Wfc, wfr, nw4);

    // K/V side via G = X^T X
    colsum<<<dim3(E_ / 32, B_), 256>>>(x);
    syrk_xtx<<<dim3(136, B_), 256, SYRK_SMEM>>>(xr);
    // yk = G @ Wk and yv = G @ Wv merged into one launch (bn split at 8)
    gemm2<<<dim3(16, 16, B_), 256, GEMM2_SMEM>>>(G, wkr, wvr, yk, yv,
                                                 E_, E_, E_, EE, 0, EE, 8, 1);
    head_build<<<dim3(BH_, 4), 256, HB_SMEM>>>(wkr);
    solver<<<BH_, 256, SOLVER_SMEM>>>(alpha, Wk, Wv, bk, bv, bq);

    // Q side collapsed: out = X @ (Wq BD(score) Wfc) + b2
    wqs_kernel<<<dim3(16, NH_, B_), 256, WQS_SMEM>>>(Wq);
    b2_build<<<dim3(E_ / 128, B_), 256>>>(Wfc, bfc);
    gemm2<<<dim3(8, 16, B_), 256, GEMM2_SMEM>>>(wqs, wfr, wfr, w2, w2,
                                                E_, E_, E_, EE, 0, EE, 8, 1);
    gemm2<<<dim3(8, 32, B_), 256, GEMM2_SMEM>>>(xr, w2, w2, out, out,
                                                S_, E_, E_, SE, EE, SE, 8, 0);
    bias_add_b2<<<(M_TOT * E_ / 4) / 256, 256>>>(out);
}

// round 13
// speedup vs baseline: 3.6165x; 2.5071x over previous
#include <cuda_runtime.h>
#include <cuda_fp16.h>
#include <mma.h>
#include <cstdint>

using namespace nvcuda;

// Problem constants
#define B_    4
#define S_    4096
#define E_    2048
#define NH_   16
#define HD_   128
#define M_TOT (B_ * S_)   // 16384
#define BH_   (B_ * NH_)  // 64

// ---------------- scratch (static device allocations; no cudaMalloc) -------
__device__ float  g_G  [(size_t)B_ * E_ * E_];   // per-batch X^T X (float)
__device__ __half g_Gh [(size_t)B_ * E_ * E_];   // half copy of G
__device__ float  g_yk [(size_t)B_ * E_ * E_];   // Gh @ Wk (float)
__device__ float  g_yv [(size_t)B_ * E_ * E_];   // Gh @ Wv (float)
__device__ __half g_wqsh[(size_t)B_ * E_ * E_];  // Wq @ blockdiag(score), half
__device__ float  g_w2 [(size_t)B_ * E_ * E_];   // Wqs @ Wfc (float)
__device__ __half g_w2h[(size_t)B_ * E_ * E_];   // half copy
__device__ __half g_xh [(size_t)M_TOT * E_];     // half x
__device__ __half g_wh [(size_t)3 * E_ * E_];    // half Wk, Wv, Wfc
__device__ float  g_s  [B_ * E_];                // column sums of X per batch
__device__ float  g_bqs[B_ * E_];                // score^T bq
__device__ float  g_b2 [B_ * E_];                // final fused bias
__device__ float  g_p1 [4 * BH_ * HD_ * HD_];    // partial Wk^T G Wk
__device__ float  g_p2 [4 * BH_ * HD_ * HD_];    // partial Wk^T G Wv
__device__ float  g_score[BH_ * HD_ * HD_];      // softmax(solve(...))

// ---------------- helpers ---------------------------------------------------
__device__ __forceinline__ void cp16(void* s, const void* g) {
    unsigned sa = (unsigned)__cvta_generic_to_shared(s);
    asm volatile("cp.async.cg.shared.global [%0], [%1], 16;" :: "r"(sa), "l"(g));
}
__device__ __forceinline__ void cp_commit() {
    asm volatile("cp.async.commit_group;");
}

// ---------------- float -> half conversion pass ----------------------------
__global__ void f2h(const float* __restrict__ in, __half* __restrict__ out, int n4) {
    int i = blockIdx.x * 256 + threadIdx.x;
    if (i >= n4) return;
    float4 v = reinterpret_cast<const float4*>(in)[i];
    __half2 h0 = __floats2half2_rn(v.x, v.y);
    __half2 h1 = __floats2half2_rn(v.z, v.w);
    reinterpret_cast<__half2*>(out)[2 * i]     = h0;
    reinterpret_cast<__half2*>(out)[2 * i + 1] = h1;
}

// ============ fp16 GEMM: 128x256 block, 64x64 warp tile, 4-stage cp.async ==
// C[z](float) = A[z](half) @ Wsel[z](half); dual mode: bn >= nbx uses (Wb, Cb).
#define BM 128
#define BN 256
#define BK 32
#define NSTG 4
#define LDA 40                        // halves (32 + 8 pad)
#define LDB 264                       // halves (256 + 8 pad)
#define A_STG (BM * LDA)              // 5120 halves
#define B_STG (BK * LDB)              // 8448 halves
#define GEMM2_SMEM (NSTG * (A_STG + B_STG) * 2)   // 108544 B

__global__ __launch_bounds__(256, 1)
void gemm2h(const __half* __restrict__ A,
            const __half* __restrict__ W, const __half* __restrict__ Wb,
            float* __restrict__ C, float* __restrict__ Cb,
            int M, int N, int K,
            long long sA, long long sB, long long sC, int nbx) {
    A += (long long)blockIdx.z * sA;
    int bn = blockIdx.x;
    const __half* Wsel; float* Csel;
    if (bn >= nbx) { Wsel = Wb; Csel = Cb; bn -= nbx; }
    else           { Wsel = W;  Csel = C; }
    Wsel += (long long)blockIdx.z * sB;
    Csel += (long long)blockIdx.z * sC;

    extern __shared__ __half smh[];
    __half* As = smh;
    __half* Bs = smh + NSTG * A_STG;
    const int tid = threadIdx.x;
    const int bm = blockIdx.y;
    const int wid = tid >> 5;
    const int wr = wid >> 2, wc = wid & 3;   // 2x4 warp grid, warp tile 64x64

    wmma::fragment<wmma::accumulator, 16, 16, 16, float> acc[4][4];
#pragma unroll
    for (int i = 0; i < 4; i++)
#pragma unroll
        for (int j = 0; j < 4; j++) wmma::fill_fragment(acc[i][j], 0.0f);

    const int KT = K / BK;
    const __half* Ab = A + (size_t)bm * BM * K;
    const __half* Bb = Wsel + (size_t)bn * BN;

    auto load_stage = [&](int kt, int buf) {
        __half* Asb = As + buf * A_STG;
        const __half* Ag = Ab + kt * BK;
#pragma unroll
        for (int p = 0; p < 2; p++) {
            int id = tid + p * 256;
            int r = id >> 2, c = (id & 3) << 3;     // 128 rows x 4 cp of 8 halves
            cp16(Asb + r * LDA + c, Ag + (size_t)r * K + c);
        }
        __half* Bsb = Bs + buf * B_STG;
        const __half* Bg = Bb + (size_t)kt * BK * N;
#pragma unroll
        for (int p = 0; p < 4; p++) {
            int id = tid + p * 256;
            int r = id >> 5, c = (id & 31) << 3;    // 32 rows x 32 cp of 8 halves
            cp16(Bsb + r * LDB + c, Bg + (size_t)r * N + c);
        }
        cp_commit();
    };

    load_stage(0, 0); load_stage(1, 1); load_stage(2, 2);

    for (int kt = 0; kt < KT; kt++) {
        if (kt + 2 < KT)      asm volatile("cp.async.wait_group 2;");
        else if (kt + 1 < KT) asm volatile("cp.async.wait_group 1;");
        else                  asm volatile("cp.async.wait_group 0;");
        __syncthreads();
        const int buf = kt % NSTG;
        const __half* Asb = As + buf * A_STG;
        const __half* Bsb = Bs + buf * B_STG;
#pragma unroll
        for (int ks = 0; ks < BK; ks += 16) {
            wmma::fragment<wmma::matrix_a, 16, 16, 16, __half, wmma::row_major> af[4];
            wmma::fragment<wmma::matrix_b, 16, 16, 16, __half, wmma::row_major> bf[4];
#pragma unroll
            for (int i = 0; i < 4; i++)
                wmma::load_matrix_sync(af[i], Asb + (wr * 64 + i * 16) * LDA + ks, LDA);
#pragma unroll
            for (int j = 0; j < 4; j++)
                wmma::load_matrix_sync(bf[j], Bsb + ks * LDB + wc * 64 + j * 16, LDB);
#pragma unroll
            for (int i = 0; i < 4; i++)
#pragma unroll
                for (int j = 0; j < 4; j++)
                    wmma::mma_sync(acc[i][j], af[i], bf[j], acc[i][j]);
        }
        if (kt + 3 < KT) load_stage(kt + 3, (kt + 3) % NSTG);
        __syncthreads();
    }

    float* Cg = Csel + (size_t)(bm * BM + wr * 64) * N + (size_t)bn * BN + wc * 64;
#pragma unroll
    for (int i = 0; i < 4; i++)
#pragma unroll
        for (int j = 0; j < 4; j++)
            wmma::store_matrix_sync(Cg + (size_t)i * 16 * N + j * 16, acc[i][j], N,
                                    wmma::mem_row_major);
}

// ---------------- column sums: s[b][e] = sum_m x[b][m][e] -------------------
__global__ void colsum(const float* __restrict__ x) {
    __shared__ float red[256];
    const int tid = threadIdx.x;
    const int tx = tid & 31, ty = tid >> 5;
    const int e = blockIdx.x * 32 + tx;
    const int b = blockIdx.y;
    const float* xb = x + (size_t)b * S_ * E_ + e;
    float acc = 0.f;
    for (int m = ty; m < S_; m += 8) acc += xb[(size_t)m * E_];
    red[ty * 32 + tx] = acc;
    __syncthreads();
    if (ty == 0) {
        float t = 0.f;
#pragma unroll
        for (int i = 0; i < 8; i++) t += red[i * 32 + tx];
        g_s[b * E_ + e] = t;
    }
}

// ------- G = Xh^T Xh (fp16 MMA; upper tiles; transposed store fills lower) -
#define SY_STG (32 * 136)                       // halves per operand stage
#define SYRK_SMEM (2 * 2 * SY_STG * 2)          // 34816 B
__global__ __launch_bounds__(256, 2)
void syrk_h(const __half* __restrict__ x) {
    int rem = blockIdx.x, i = 0;
    while (rem >= 16 - i) { rem -= (16 - i); i++; }
    const int j = i + rem;
    const int b = blockIdx.y;
    extern __shared__ __half smh[];
    __half* As = smh;
    __half* Bs = smh + 2 * SY_STG;
    const int tid = threadIdx.x;
    const int wid = tid >> 5, wr = wid >> 1, wc = wid & 1;

    const __half* ai = x + (size_t)b * S_ * E_ + i * 128;
    const __half* bj = x + (size_t)b * S_ * E_ + j * 128;

    wmma::fragment<wmma::accumulator, 16, 16, 16, float> acc[2][4];
#pragma unroll
    for (int p = 0; p < 2; p++)
#pragma unroll
        for (int q = 0; q < 4; q++) wmma::fill_fragment(acc[p][q], 0.0f);

    auto load_stage = [&](int it, int buf) {
        const int ss = it * 32;
#pragma unroll
        for (int p = 0; p < 2; p++) {
            int id = tid + p * 256;
            int r = id >> 4, c = (id & 15) << 3;   // 32 rows x 16 cp of 8 halves
            cp16(As + buf * SY_STG + r * 136 + c, ai + (size_t)(ss + r) * E_ + c);
            cp16(Bs + buf * SY_STG + r * 136 + c, bj + (size_t)(ss + r) * E_ + c);
        }
        cp_commit();
    };

    const int IT = S_ / 32;   // 128
    load_stage(0, 0);
    for (int it = 0; it < IT; it++) {
        if (it + 1 < IT) { load_stage(it + 1, (it + 1) & 1);
                           asm volatile("cp.async.wait_group 1;"); }
        else             { asm volatile("cp.async.wait_group 0;"); }
        __syncthreads();
        const __half* Asb = As + (it & 1) * SY_STG;
        const __half* Bsb = Bs + (it & 1) * SY_STG;
#pragma unroll
        for (int ks = 0; ks < 32; ks += 16) {
            wmma::fragment<wmma::matrix_a, 16, 16, 16, __half, wmma::col_major> af[2];
#pragma unroll
            for (int p = 0; p < 2; p++)
                wmma::load_matrix_sync(af[p], Asb + ks * 136 + wr * 32 + p * 16, 136);
#pragma unroll
            for (int q = 0; q < 4; q++) {
                wmma::fragment<wmma::matrix_b, 16, 16, 16, __half, wmma::row_major> bf;
                wmma::load_matrix_sync(bf, Bsb + ks * 136 + wc * 64 + q * 16, 136);
                wmma::mma_sync(acc[0][q], af[0], bf, acc[0][q]);
                wmma::mma_sync(acc[1][q], af[1], bf, acc[1][q]);
            }
        }
        __syncthreads();
    }

    float* Gb = g_G + (size_t)b * E_ * E_;
#pragma unroll
    for (int p = 0; p < 2; p++)
#pragma unroll
        for (int q = 0; q < 4; q++) {
            int rr = wr * 32 + p * 16, cc = wc * 64 + q * 16;
            wmma::store_matrix_sync(Gb + (size_t)(i * 128 + rr) * E_ + j * 128 + cc,
                                    acc[p][q], E_, wmma::mem_row_major);
            if (i != j)
                wmma::store_matrix_sync(Gb + (size_t)(j * 128 + cc) * E_ + i * 128 + rr,
                                        acc[p][q], E_, wmma::mem_col_major);
        }
}

// --------- per-head raw mats: p1 = Wk_h^T Yk[:,h], p2 = Wk_h^T Yv[:,h] -----
// tf32 on raw floats (HW truncation) — feeds only the softmax-diluted path.
#define HB_STG (3 * 32 * 136)
#define HB_SMEM (2 * HB_STG * sizeof(float))
__global__ void head_build(const float* __restrict__ Wk) {
    const int bh = blockIdx.x, chunk = blockIdx.y;
    const int b = bh >> 4, h = bh & 15;
    extern __shared__ float sm[];
    const int tid = threadIdx.x;
    const int wid = tid >> 5, wr = wid >> 1, wc = wid & 1;

    const float* wbase = Wk + h * 128;
    const float* ykb = g_yk + (size_t)b * E_ * E_ + h * 128;
    const float* yvb = g_yv + (size_t)b * E_ * E_ + h * 128;
    const int k0 = chunk * 512;

    wmma::fragment<wmma::accumulator, 16, 16, 8, float> acck[2][4], accv[2][4];
#pragma unroll
    for (int p = 0; p < 2; p++)
#pragma unroll
        for (int q = 0; q < 4; q++) {
            wmma::fill_fragment(acck[p][q], 0.0f);
            wmma::fill_fragment(accv[p][q], 0.0f);
        }

    auto load_stage = [&](int it, int buf) {
        float* base = sm + buf * HB_STG;
        const int ss = k0 + it * 32;
#pragma unroll
        for (int p = 0; p < 4; p++) {
            int id = tid + p * 256;
            int r = id >> 5, c = (id & 31) << 2;
            size_t row = (size_t)(ss + r) * E_;
            cp16(base + r * 136 + c,        wbase + row + c);
            cp16(base + 4352 + r * 136 + c, ykb + row + c);
            cp16(base + 8704 + r * 136 + c, yvb + row + c);
        }
        cp_commit();
    };

    const int IT = 16;
    load_stage(0, 0);
    for (int it = 0; it < IT; it++) {
        if (it + 1 < IT) { load_stage(it + 1, (it + 1) & 1);
                           asm volatile("cp.async.wait_group 1;"); }
        else             { asm volatile("cp.async.wait_group 0;"); }
        __syncthreads();
        const float* base = sm + (it & 1) * HB_STG;
        const float* Ws = base;
        const float* Yks = base + 4352;
        const float* Yvs = base + 8704;
#pragma unroll
        for (int ks = 0; ks < 32; ks += 8) {
            wmma::fragment<wmma::matrix_a, 16, 16, 8, wmma::precision::tf32, wmma::col_major> af[2];
#pragma unroll
            for (int p = 0; p < 2; p++)
                wmma::load_matrix_sync(af[p], Ws + ks * 136 + wr * 32 + p * 16, 136);
#pragma unroll
            for (int q = 0; q < 4; q++) {
                wmma::fragment<wmma::matrix_b, 16, 16, 8, wmma::precision::tf32, wmma::row_major> bf;
                wmma::load_matrix_sync(bf, Yks + ks * 136 + wc * 64 + q * 16, 136);
                wmma::mma_sync(acck[0][q], af[0], bf, acck[0][q]);
                wmma::mma_sync(acck[1][q], af[1], bf, acck[1][q]);
                wmma::load_matrix_sync(bf, Yvs + ks * 136 + wc * 64 + q * 16, 136);
                wmma::mma_sync(accv[0][q], af[0], bf, accv[0][q]);
                wmma::mma_sync(accv[1][q], af[1], bf, accv[1][q]);
            }
        }
        __syncthreads();
    }
    float* p1 = g_p1 + ((size_t)chunk * BH_ + bh) * (HD_ * HD_);
    float* p2 = g_p2 + ((size_t)chunk * BH_ + bh) * (HD_ * HD_);
#pragma unroll
    for (int p = 0; p < 2; p++)
#pragma unroll
        for (int q = 0; q < 4; q++) {
            wmma::store_matrix_sync(p1 + (wr * 32 + p * 16) * HD_ + wc * 64 + q * 16,
                                    acck[p][q], HD_, wmma::mem_row_major);
            wmma::store_matrix_sync(p2 + (wr * 32 + p * 16) * HD_ + wc * 64 + q * 16,
                                    accv[p][q], HD_, wmma::mem_row_major);
        }
}

// -------- solver: bias rank-1s + alpha*I, Cholesky solve, softmax, bqs -----
#define SOLVER_SMEM ((2 * 128 * 129 + 6 * 128 + 512) * sizeof(float))
__global__ void solver(const float* __restrict__ alpha,
                       const float* __restrict__ Wk, const float* __restrict__ Wv,
                       const float* __restrict__ bk, const float* __restrict__ bv,
                       const float* __restrict__ bq) {
    const int bh = blockIdx.x;
    const int b = bh >> 4, h = bh & 15;
    const int tid = threadIdx.x;
    extern __shared__ float sm[];
    float* Am  = sm;
    float* Bm  = Am + 128 * 129;
    float* uK  = Bm + 128 * 129;
    float* uV  = uK + 128;
    float* bks = uV + 128;
    float* bvs = bks + 128;
    float* bqv = bvs + 128;
    float* sinv = bqv + 128;
    float* uKp = sinv + 128;
    float* uVp = uKp + 256;

    {
        const int c = tid & 127, half = tid >> 7;
        const float* sb = g_s + b * E_;
        const float* pk = Wk + h * 128 + c;
        const float* pv = Wv + h * 128 + c;
        float ak = 0.f, av = 0.f;
#pragma unroll 8
        for (int k = half * 1024; k < half * 1024 + 1024; k++) {
            float sv = sb[k];
            ak += pk[(size_t)k * E_] * sv;
            av += pv[(size_t)k * E_] * sv;
        }
        uKp[half * 128 + c] = ak;
        uVp[half * 128 + c] = av;
        if (tid < 128) {
            bks[tid] = bk[h * 128 + tid];
            bvs[tid] = bv[h * 128 + tid];
            bqv[tid] = bq[h * 128 + tid];
        }
    }
    __syncthreads();
    if (tid < 128) {
        uK[tid] = uKp[tid] + uKp[128 + tid];
        uV[tid] = uVp[tid] + uVp[128 + tid];
    }
    __syncthreads();

    const float a = alpha[0];
    for (int i = tid; i < HD_ * HD_; i += 256) {
        int r = i >> 7, c = i & 127;
        float s1 = 0.f, s2 = 0.f;
#pragma unroll
        for (int ch = 0; ch < 4; ch++) {
            s1 += g_p1[((size_t)ch * BH_ + bh) * (HD_ * HD_) + i];
            s2 += g_p2[((size_t)ch * BH_ + bh) * (HD_ * HD_) + i];
        }
        Am[r * 129 + c] = s1 + uK[r] * bks[c] + bks[r] * uK[c]
                          + (float)S_ * bks[r] * bks[c] + ((r == c) ? a : 0.f);
        Bm[r * 129 + c] = s2 + uK[r] * bvs[c] + bks[r] * uV[c]
                          + (float)S_ * bks[r] * bvs[c];
    }
    __syncthreads();

    for (int j = 0; j < HD_; j++) {
        if (tid == 0) Am[j * 129 + j] = sqrtf(Am[j * 129 + j]);
        __syncthreads();
        float dinv = 1.0f / Am[j * 129 + j];
        int n = 127 - j;
        for (int i = tid; i < n; i += 256) Am[(j + 1 + i) * 129 + j] *= dinv;
        __syncthreads();
        int tot = n * n;
        for (int t = tid; t < tot; t += 256) {
            int ri = j + 1 + t / n, ci = j + 1 + t % n;
            Am[ri * 129 + ci] -= Am[ri * 129 + j] * Am[ci * 129 + j];
        }
        __syncthreads();
    }

    if (tid < 128) {
        const int c = tid;
        for (int i = 0; i < 128; i++) {
            float t = Bm[i * 129 + c];
            for (int j2 = 0; j2 < i; j2++) t -= Am[i * 129 + j2] * Bm[j2 * 129 + c];
            Bm[i * 129 + c] = t / Am[i * 129 + i];
        }
        for (int i = 127; i >= 0; i--) {
            float t = Bm[i * 129 + c];
            for (int j2 = i + 1; j2 < 128; j2++) t -= Am[j2 * 129 + i] * Bm[j2 * 129 + c];
            Bm[i * 129 + c] = t / Am[i * 129 + i];
        }
    }
    __syncthreads();

    if (tid < 128) {
        const int r = tid;
        float m = -1e30f;
        for (int c = 0; c < 128; c++) m = fmaxf(m, Bm[r * 129 + c]);
        float s = 0.f;
        for (int c = 0; c < 128; c++) {
            float e = expf(Bm[r * 129 + c] - m);
            Bm[r * 129 + c] = e;
            s += e;
        }
        float inv = 1.0f / s;
        sinv[r] = inv;
        for (int c = 0; c < 128; c++)
            g_score[(size_t)bh * (HD_ * HD_) + r * HD_ + c] = Bm[r * 129 + c] * inv;
    }
    __syncthreads();

    if (tid < 128) {
        const int c = tid;
        float acc = 0.f;
        for (int r = 0; r < 128; r++) acc += bqv[r] * Bm[r * 129 + c] * sinv[r];
        g_bqs[b * E_ + h * 128 + c] = acc;
    }
}

// ------ Wqs[:, hblk] = Wq[:, hblk] @ score_bh  (fp32 SIMT -> half store) ---
#define WQS_SMEM (128 * 132 * sizeof(float))
__global__ void wqs_kernel(const float* __restrict__ Wq) {
    const int bx = blockIdx.x, h = blockIdx.y, b = blockIdx.z;
    extern __shared__ float sc[];  // [128][132]
    const int tid = threadIdx.x;
    const float* sg = g_score + (size_t)(b * NH_ + h) * (HD_ * HD_);
    for (int i = tid; i < 128 * 128; i += 256) {
        int r = i >> 7, c = i & 127;
        sc[r * 132 + c] = sg[i];
    }
    __syncthreads();

    const int pr = tid >> 4, pc = tid & 15;  // 16x16 patches of 8x8
    const float* wrow = Wq + (size_t)(bx * 128 + pr * 8) * E_ + h * 128;
    float acc[8][8];
#pragma unroll
    for (int i = 0; i < 8; i++)
#pragma unroll
        for (int j = 0; j < 8; j++) acc[i][j] = 0.f;

    for (int k = 0; k < 128; k++) {
        float w8[8];
#pragma unroll
        for (int i = 0; i < 8; i++) w8[i] = wrow[(size_t)i * E_ + k];
        float4 s0 = *reinterpret_cast<const float4*>(&sc[k * 132 + pc * 8]);
        float4 s1 = *reinterpret_cast<const float4*>(&sc[k * 132 + pc * 8 + 4]);
        float s8[8] = {s0.x, s0.y, s0.z, s0.w, s1.x, s1.y, s1.z, s1.w};
#pragma unroll
        for (int i = 0; i < 8; i++)
#pragma unroll
            for (int j = 0; j < 8; j++) acc[i][j] += w8[i] * s8[j];
    }

    __half* og = g_wqsh + (size_t)b * E_ * E_ + (size_t)(bx * 128 + pr * 8) * E_
                 + h * 128 + pc * 8;
#pragma unroll
    for (int i = 0; i < 8; i++) {
        __half2* p = reinterpret_cast<__half2*>(og + (size_t)i * E_);
        p[0] = __floats2half2_rn(acc[i][0], acc[i][1]);
        p[1] = __floats2half2_rn(acc[i][2], acc[i][3]);
        p[2] = __floats2half2_rn(acc[i][4], acc[i][5]);
        p[3] = __floats2half2_rn(acc[i][6], acc[i][7]);
    }
}

// ------ b2[b][n] = sum_k bqs[b][k] * Wfc[k][n] + bfc[n]  (k-parallel) ------
__global__ void b2_build(const float* __restrict__ Wfc, const float* __restrict__ bfc) {
    __shared__ float part[2][128];
    const int tid = threadIdx.x;
    const int nl = tid & 127, half = tid >> 7;
    const int n = blockIdx.x * 128 + nl;
    const int b = blockIdx.y;
    const float* bqs = g_bqs + b * E_;
    float acc = 0.f;
#pragma unroll 8
    for (int k = half * 1024; k < half * 1024 + 1024; k++)
        acc += bqs[k] * Wfc[(size_t)k * E_ + n];
    part[half][nl] = acc;
    __syncthreads();
    if (tid < 128)
        g_b2[b * E_ + n] = part[0][nl] + part[1][nl] + bfc[n];
}

// ------ out += b2 (per batch) ----------------------------------------------
__global__ void bias_add_b2(float* __restrict__ C) {
    int i = blockIdx.x * 256 + threadIdx.x;
    int batch = i >> 21;
    int nb = i & (E_ / 4 - 1);
    float4 c = reinterpret_cast<float4*>(C)[i];
    float4 bb = reinterpret_cast<const float4*>(g_b2 + batch * E_)[nb];
    c.x += bb.x; c.y += bb.y; c.z += bb.z; c.w += bb.w;
    reinterpret_cast<float4*>(C)[i] = c;
}

// ---------------- host entry ------------------------------------------------
extern "C" void kernel_launch(void* const* d_in, const int* in_sizes, int n_in,
                              void* d_out, int out_size) {
    (void)in_sizes; (void)n_in; (void)out_size;
    const float* x     = (const float*)d_in[0];
    const float* alpha = (const float*)d_in[1];
    const float* Wq    = (const float*)d_in[2];
    const float* bq    = (const float*)d_in[3];
    const float* Wk    = (const float*)d_in[4];
    const float* bk    = (const float*)d_in[5];
    const float* Wv    = (const float*)d_in[6];
    const float* bv    = (const float*)d_in[7];
    const float* Wfc   = (const float*)d_in[8];
    const float* bfc   = (const float*)d_in[9];
    float* out = (float*)d_out;

    float *G, *yk, *yv, *w2;
    __half *Gh, *xh, *wh, *wqsh, *w2h;
    cudaGetSymbolAddress((void**)&G,    g_G);
    cudaGetSymbolAddress((void**)&Gh,   g_Gh);
    cudaGetSymbolAddress((void**)&yk,   g_yk);
    cudaGetSymbolAddress((void**)&yv,   g_yv);
    cudaGetSymbolAddress((void**)&w2,   g_w2);
    cudaGetSymbolAddress((void**)&w2h,  g_w2h);
    cudaGetSymbolAddress((void**)&xh,   g_xh);
    cudaGetSymbolAddress((void**)&wh,   g_wh);
    cudaGetSymbolAddress((void**)&wqsh, g_wqsh);

    cudaFuncSetAttribute(gemm2h, cudaFuncAttributeMaxDynamicSharedMemorySize, GEMM2_SMEM);
    cudaFuncSetAttribute(syrk_h, cudaFuncAttributeMaxDynamicSharedMemorySize, SYRK_SMEM);
    cudaFuncSetAttribute(head_build, cudaFuncAttributeMaxDynamicSharedMemorySize, HB_SMEM);
    cudaFuncSetAttribute(solver, cudaFuncAttributeMaxDynamicSharedMemorySize, SOLVER_SMEM);
    cudaFuncSetAttribute(wqs_kernel, cudaFuncAttributeMaxDynamicSharedMemorySize, WQS_SMEM);

    const long long EE = (long long)E_ * E_;
    const long long SE = (long long)S_ * E_;
    const int nx4 = M_TOT * E_ / 4;      // 8388608
    const int nw4 = E_ * E_ / 4;         // 1048576
    const int nG4 = B_ * E_ * E_ / 4;    // 4194304
    __half* wkh = wh + 0 * EE;
    __half* wvh = wh + 1 * EE;
    __half* wfh = wh + 2 * EE;

    // half conversions (rn rounding; same mantissa width as tf32)
    f2h<<<nx4 / 256, 256>>>(x, xh, nx4);
    f2h<<<nw4 / 256, 256>>>(Wk, wkh, nw4);
    f2h<<<nw4 / 256, 256>>>(Wv, wvh, nw4);
    f2h<<<nw4 / 256, 256>>>(Wfc, wfh, nw4);

    // K/V side via G = X^T X
    colsum<<<dim3(E_ / 32, B_), 256>>>(x);
    syrk_h<<<dim3(136, B_), 256, SYRK_SMEM>>>(xh);
    f2h<<<nG4 / 256, 256>>>(G, Gh, nG4);
    // yk = G @ Wk and yv = G @ Wv in one launch (bn split at 8)
    gemm2h<<<dim3(16, 16, B_), 256, GEMM2_SMEM>>>(Gh, wkh, wvh, yk, yv,
                                                  E_, E_, E_, EE, 0, EE, 8);
    head_build<<<dim3(BH_, 4), 256, HB_SMEM>>>(Wk);
    solver<<<BH_, 256, SOLVER_SMEM>>>(alpha, Wk, Wv, bk, bv, bq);

    // Q side collapsed: out = X @ (Wq BD(score) Wfc) + b2
    wqs_kernel<<<dim3(16, NH_, B_), 256, WQS_SMEM>>>(Wq);
    b2_build<<<dim3(E_ / 128, B_), 256>>>(Wfc, bfc);
    gemm2h<<<dim3(8, 16, B_), 256, GEMM2_SMEM>>>(wqsh, wfh, wfh, w2, w2,
                                                 E_, E_, E_, EE, 0, EE, 8);
    f2h<<<nG4 / 256, 256>>>(w2, w2h, nG4);
    gemm2h<<<dim3(8, 32, B_), 256, GEMM2_SMEM>>>(xh, w2h, w2h, out, out,
                                                 S_, E_, E_, SE, EE, SE, 8);
    bias_add_b2<<<(M_TOT * E_ / 4) / 256, 256>>>(out);
}

// round 16
// speedup vs baseline: 4.0227x; 1.1123x over previous
#include <cuda_runtime.h>
#include <cuda_fp16.h>
#include <mma.h>
#include <cstdint>

using namespace nvcuda;

// Problem constants
#define B_    4
#define S_    4096
#define E_    2048
#define NH_   16
#define HD_   128
#define M_TOT (B_ * S_)   // 16384
#define BH_   (B_ * NH_)  // 64

// ---------------- scratch (static device allocations; no cudaMalloc) -------
__device__ float  g_G  [(size_t)B_ * E_ * E_];   // per-batch X^T X (float)
__device__ __half g_Gh [(size_t)B_ * E_ * E_];   // half copy of G
__device__ float  g_yk [(size_t)B_ * E_ * E_];   // G @ Wk (float)
__device__ __half g_ykh[(size_t)B_ * E_ * E_];   // half copy of yk
__device__ __half g_wqsh[(size_t)B_ * E_ * E_];  // Wq @ blockdiag(score), half
__device__ float  g_w2 [(size_t)B_ * E_ * E_];   // Wqs @ Wfc (float)
__device__ __half g_w2h[(size_t)B_ * E_ * E_];   // half copy
__device__ __half g_xh [(size_t)M_TOT * E_];     // half x
__device__ __half g_wh [(size_t)3 * E_ * E_];    // half Wk, Wv, Wfc
__device__ float  g_s  [B_ * E_];                // column sums of X per batch
__device__ float  g_bqs[B_ * E_];                // score^T bq
__device__ float  g_b2 [B_ * E_];                // final fused bias
__device__ float  g_p1 [4 * BH_ * HD_ * HD_];    // partial Wk^T G Wk
__device__ float  g_p2 [4 * BH_ * HD_ * HD_];    // partial Wk^T G Wv
__device__ float  g_score[BH_ * HD_ * HD_];      // softmax(solve(...))

// ---------------- helpers ---------------------------------------------------
__device__ __forceinline__ void cp16(void* s, const void* g) {
    unsigned sa = (unsigned)__cvta_generic_to_shared(s);
    asm volatile("cp.async.cg.shared.global [%0], [%1], 16;" :: "r"(sa), "l"(g));
}
__device__ __forceinline__ void cp_commit() {
    asm volatile("cp.async.commit_group;");
}

// ---------------- float -> half conversion pass ----------------------------
__global__ void f2h(const float* __restrict__ in, __half* __restrict__ out, int n4) {
    int i = blockIdx.x * 256 + threadIdx.x;
    if (i >= n4) return;
    float4 v = reinterpret_cast<const float4*>(in)[i];
    __half2 h0 = __floats2half2_rn(v.x, v.y);
    __half2 h1 = __floats2half2_rn(v.z, v.w);
    reinterpret_cast<__half2*>(out)[2 * i]     = h0;
    reinterpret_cast<__half2*>(out)[2 * i + 1] = h1;
}

// ============ fp16 GEMM: 128x256 block, 64x64 warp tile, 4-stage cp.async ==
// C[z](float) = A[z](half) @ Wsel[z](half); dual mode: bn >= nbx uses (Wb, Cb).
#define BM 128
#define BN 256
#define BK 32
#define NSTG 4
#define LDA 40                        // halves (32 + 8 pad)
#define LDB 264                       // halves (256 + 8 pad)
#define A_STG (BM * LDA)              // 5120 halves
#define B_STG (BK * LDB)              // 8448 halves
#define GEMM2_SMEM (NSTG * (A_STG + B_STG) * 2)   // 108544 B

__global__ __launch_bounds__(256, 1)
void gemm2h(const __half* __restrict__ A,
            const __half* __restrict__ W, const __half* __restrict__ Wb,
            float* __restrict__ C, float* __restrict__ Cb,
            int M, int N, int K,
            long long sA, long long sB, long long sC, int nbx) {
    A += (long long)blockIdx.z * sA;
    int bn = blockIdx.x;
    const __half* Wsel; float* Csel;
    if (bn >= nbx) { Wsel = Wb; Csel = Cb; bn -= nbx; }
    else           { Wsel = W;  Csel = C; }
    Wsel += (long long)blockIdx.z * sB;
    Csel += (long long)blockIdx.z * sC;

    extern __shared__ __half smh[];
    __half* As = smh;
    __half* Bs = smh + NSTG * A_STG;
    const int tid = threadIdx.x;
    const int bm = blockIdx.y;
    const int wid = tid >> 5;
    const int wr = wid >> 2, wc = wid & 3;   // 2x4 warp grid, warp tile 64x64

    wmma::fragment<wmma::accumulator, 16, 16, 16, float> acc[4][4];
#pragma unroll
    for (int i = 0; i < 4; i++)
#pragma unroll
        for (int j = 0; j < 4; j++) wmma::fill_fragment(acc[i][j], 0.0f);

    const int KT = K / BK;
    const __half* Ab = A + (size_t)bm * BM * K;
    const __half* Bb = Wsel + (size_t)bn * BN;

    auto load_stage = [&](int kt, int buf) {
        __half* Asb = As + buf * A_STG;
        const __half* Ag = Ab + kt * BK;
#pragma unroll
        for (int p = 0; p < 2; p++) {
            int id = tid + p * 256;
            int r = id >> 2, c = (id & 3) << 3;     // 128 rows x 4 cp of 8 halves
            cp16(Asb + r * LDA + c, Ag + (size_t)r * K + c);
        }
        __half* Bsb = Bs + buf * B_STG;
        const __half* Bg = Bb + (size_t)kt * BK * N;
#pragma unroll
        for (int p = 0; p < 4; p++) {
            int id = tid + p * 256;
            int r = id >> 5, c = (id & 31) << 3;    // 32 rows x 32 cp of 8 halves
            cp16(Bsb + r * LDB + c, Bg + (size_t)r * N + c);
        }
        cp_commit();
    };

    load_stage(0, 0); load_stage(1, 1); load_stage(2, 2);

    for (int kt = 0; kt < KT; kt++) {
        if (kt + 2 < KT)      asm volatile("cp.async.wait_group 2;");
        else if (kt + 1 < KT) asm volatile("cp.async.wait_group 1;");
        else                  asm volatile("cp.async.wait_group 0;");
        __syncthreads();
        const int buf = kt % NSTG;
        const __half* Asb = As + buf * A_STG;
        const __half* Bsb = Bs + buf * B_STG;
#pragma unroll
        for (int ks = 0; ks < BK; ks += 16) {
            wmma::fragment<wmma::matrix_a, 16, 16, 16, __half, wmma::row_major> af[4];
            wmma::fragment<wmma::matrix_b, 16, 16, 16, __half, wmma::row_major> bf[4];
#pragma unroll
            for (int i = 0; i < 4; i++)
                wmma::load_matrix_sync(af[i], Asb + (wr * 64 + i * 16) * LDA + ks, LDA);
#pragma unroll
            for (int j = 0; j < 4; j++)
                wmma::load_matrix_sync(bf[j], Bsb + ks * LDB + wc * 64 + j * 16, LDB);
#pragma unroll
            for (int i = 0; i < 4; i++)
#pragma unroll
                for (int j = 0; j < 4; j++)
                    wmma::mma_sync(acc[i][j], af[i], bf[j], acc[i][j]);
        }
        if (kt + 3 < KT) load_stage(kt + 3, (kt + 3) % NSTG);
        __syncthreads();
    }

    float* Cg = Csel + (size_t)(bm * BM + wr * 64) * N + (size_t)bn * BN + wc * 64;
#pragma unroll
    for (int i = 0; i < 4; i++)
#pragma unroll
        for (int j = 0; j < 4; j++)
            wmma::store_matrix_sync(Cg + (size_t)i * 16 * N + j * 16, acc[i][j], N,
                                    wmma::mem_row_major);
}

// ---------------- column sums: s[b][e] = sum_m x[b][m][e] -------------------
__global__ void colsum(const float* __restrict__ x) {
    __shared__ float red[256];
    const int tid = threadIdx.x;
    const int tx = tid & 31, ty = tid >> 5;
    const int e = blockIdx.x * 32 + tx;
    const int b = blockIdx.y;
    const float* xb = x + (size_t)b * S_ * E_ + e;
    float acc = 0.f;
    for (int m = ty; m < S_; m += 8) acc += xb[(size_t)m * E_];
    red[ty * 32 + tx] = acc;
    __syncthreads();
    if (ty == 0) {
        float t = 0.f;
#pragma unroll
        for (int i = 0; i < 8; i++) t += red[i * 32 + tx];
        g_s[b * E_ + e] = t;
    }
}

// ------- G = Xh^T Xh (fp16 MMA; upper tiles; transposed store fills lower) -
#define SY_STG (32 * 136)                       // halves per operand stage
#define SYRK_SMEM (2 * 2 * SY_STG * 2)          // 34816 B
__global__ __launch_bounds__(256, 2)
void syrk_h(const __half* __restrict__ x) {
    int rem = blockIdx.x, i = 0;
    while (rem >= 16 - i) { rem -= (16 - i); i++; }
    const int j = i + rem;
    const int b = blockIdx.y;
    extern __shared__ __half smh[];
    __half* As = smh;
    __half* Bs = smh + 2 * SY_STG;
    const int tid = threadIdx.x;
    const int wid = tid >> 5, wr = wid >> 1, wc = wid & 1;

    const __half* ai = x + (size_t)b * S_ * E_ + i * 128;
    const __half* bj = x + (size_t)b * S_ * E_ + j * 128;

    wmma::fragment<wmma::accumulator, 16, 16, 16, float> acc[2][4];
#pragma unroll
    for (int p = 0; p < 2; p++)
#pragma unroll
        for (int q = 0; q < 4; q++) wmma::fill_fragment(acc[p][q], 0.0f);

    auto load_stage = [&](int it, int buf) {
        const int ss = it * 32;
#pragma unroll
        for (int p = 0; p < 2; p++) {
            int id = tid + p * 256;
            int r = id >> 4, c = (id & 15) << 3;   // 32 rows x 16 cp of 8 halves
            cp16(As + buf * SY_STG + r * 136 + c, ai + (size_t)(ss + r) * E_ + c);
            cp16(Bs + buf * SY_STG + r * 136 + c, bj + (size_t)(ss + r) * E_ + c);
        }
        cp_commit();
    };

    const int IT = S_ / 32;   // 128
    load_stage(0, 0);
    for (int it = 0; it < IT; it++) {
        if (it + 1 < IT) { load_stage(it + 1, (it + 1) & 1);
                           asm volatile("cp.async.wait_group 1;"); }
        else             { asm volatile("cp.async.wait_group 0;"); }
        __syncthreads();
        const __half* Asb = As + (it & 1) * SY_STG;
        const __half* Bsb = Bs + (it & 1) * SY_STG;
#pragma unroll
        for (int ks = 0; ks < 32; ks += 16) {
            wmma::fragment<wmma::matrix_a, 16, 16, 16, __half, wmma::col_major> af[2];
#pragma unroll
            for (int p = 0; p < 2; p++)
                wmma::load_matrix_sync(af[p], Asb + ks * 136 + wr * 32 + p * 16, 136);
#pragma unroll
            for (int q = 0; q < 4; q++) {
                wmma::fragment<wmma::matrix_b, 16, 16, 16, __half, wmma::row_major> bf;
                wmma::load_matrix_sync(bf, Bsb + ks * 136 + wc * 64 + q * 16, 136);
                wmma::mma_sync(acc[0][q], af[0], bf, acc[0][q]);
                wmma::mma_sync(acc[1][q], af[1], bf, acc[1][q]);
            }
        }
        __syncthreads();
    }

    float* Gb = g_G + (size_t)b * E_ * E_;
#pragma unroll
    for (int p = 0; p < 2; p++)
#pragma unroll
        for (int q = 0; q < 4; q++) {
            int rr = wr * 32 + p * 16, cc = wc * 64 + q * 16;
            wmma::store_matrix_sync(Gb + (size_t)(i * 128 + rr) * E_ + j * 128 + cc,
                                    acc[p][q], E_, wmma::mem_row_major);
            if (i != j)
                wmma::store_matrix_sync(Gb + (size_t)(j * 128 + cc) * E_ + i * 128 + rr,
                                        acc[p][q], E_, wmma::mem_col_major);
        }
}

// --------- per-head raw mats via symmetry (fp16):
//   p1_h = yk_h^T @ Wk_h  ( = Wk_h^T G Wk_h )
//   p2_h = yk_h^T @ Wv_h  ( = Wk_h^T G Wv_h, G symmetric )
#define HBH_STG (3 * 32 * 136)                 // halves
#define HBH_SMEM (2 * HBH_STG * 2)             // 52224 B
__global__ void head_build_h(const __half* __restrict__ wkh,
                             const __half* __restrict__ wvh) {
    const int bh = blockIdx.x, chunk = blockIdx.y;
    const int b = bh >> 4, h = bh & 15;
    extern __shared__ __half smh[];
    const int tid = threadIdx.x;
    const int wid = tid >> 5, wr = wid >> 1, wc = wid & 1;

    const __half* ykb = g_ykh + (size_t)b * E_ * E_ + h * 128;
    const __half* kb  = wkh + h * 128;
    const __half* vb  = wvh + h * 128;
    const int k0 = chunk * 512;

    wmma::fragment<wmma::accumulator, 16, 16, 16, float> acck[2][4], accv[2][4];
#pragma unroll
    for (int p = 0; p < 2; p++)
#pragma unroll
        for (int q = 0; q < 4; q++) {
            wmma::fill_fragment(acck[p][q], 0.0f);
            wmma::fill_fragment(accv[p][q], 0.0f);
        }

    auto load_stage = [&](int it, int buf) {
        __half* base = smh + buf * HBH_STG;
        const int ss = k0 + it * 32;
#pragma unroll
        for (int p = 0; p < 2; p++) {
            int id = tid + p * 256;
            int r = id >> 4, c = (id & 15) << 3;   // 32 rows x 16 cp of 8 halves
            size_t row = (size_t)(ss + r) * E_;
            cp16(base + r * 136 + c,        ykb + row + c);
            cp16(base + 4352 + r * 136 + c, kb + row + c);
            cp16(base + 8704 + r * 136 + c, vb + row + c);
        }
        cp_commit();
    };

    const int IT = 16;  // 512 / 32
    load_stage(0, 0);
    for (int it = 0; it < IT; it++) {
        if (it + 1 < IT) { load_stage(it + 1, (it + 1) & 1);
                           asm volatile("cp.async.wait_group 1;"); }
        else             { asm volatile("cp.async.wait_group 0;"); }
        __syncthreads();
        const __half* base = smh + (it & 1) * HBH_STG;
        const __half* Ys = base;          // yk slice (A^T via col_major)
        const __half* Ks = base + 4352;   // Wk slice
        const __half* Vs = base + 8704;   // Wv slice
#pragma unroll
        for (int ks = 0; ks < 32; ks += 16) {
            wmma::fragment<wmma::matrix_a, 16, 16, 16, __half, wmma::col_major> af[2];
#pragma unroll
            for (int p = 0; p < 2; p++)
                wmma::load_matrix_sync(af[p], Ys + ks * 136 + wr * 32 + p * 16, 136);
#pragma unroll
            for (int q = 0; q < 4; q++) {
                wmma::fragment<wmma::matrix_b, 16, 16, 16, __half, wmma::row_major> bf;
                wmma::load_matrix_sync(bf, Ks + ks * 136 + wc * 64 + q * 16, 136);
                wmma::mma_sync(acck[0][q], af[0], bf, acck[0][q]);
                wmma::mma_sync(acck[1][q], af[1], bf, acck[1][q]);
                wmma::load_matrix_sync(bf, Vs + ks * 136 + wc * 64 + q * 16, 136);
                wmma::mma_sync(accv[0][q], af[0], bf, accv[0][q]);
                wmma::mma_sync(accv[1][q], af[1], bf, accv[1][q]);
            }
        }
        __syncthreads();
    }
    float* p1 = g_p1 + ((size_t)chunk * BH_ + bh) * (HD_ * HD_);
    float* p2 = g_p2 + ((size_t)chunk * BH_ + bh) * (HD_ * HD_);
#pragma unroll
    for (int p = 0; p < 2; p++)
#pragma unroll
        for (int q = 0; q < 4; q++) {
            wmma::store_matrix_sync(p1 + (wr * 32 + p * 16) * HD_ + wc * 64 + q * 16,
                                    acck[p][q], HD_, wmma::mem_row_major);
            wmma::store_matrix_sync(p2 + (wr * 32 + p * 16) * HD_ + wc * 64 + q * 16,
                                    accv[p][q], HD_, wmma::mem_row_major);
        }
}

// -------- solver: bias rank-1s + alpha*I, Cholesky solve, softmax, bqs -----
#define SOLVER_SMEM ((2 * 128 * 129 + 6 * 128 + 512) * sizeof(float))
__global__ void solver(const float* __restrict__ alpha,
                       const float* __restrict__ Wk, const float* __restrict__ Wv,
                       const float* __restrict__ bk, const float* __restrict__ bv,
                       const float* __restrict__ bq) {
    const int bh = blockIdx.x;
    const int b = bh >> 4, h = bh & 15;
    const int tid = threadIdx.x;
    extern __shared__ float sm[];
    float* Am  = sm;
    float* Bm  = Am + 128 * 129;
    float* uK  = Bm + 128 * 129;
    float* uV  = uK + 128;
    float* bks = uV + 128;
    float* bvs = bks + 128;
    float* bqv = bvs + 128;
    float* sinv = bqv + 128;
    float* uKp = sinv + 128;
    float* uVp = uKp + 256;

    {
        const int c = tid & 127, half = tid >> 7;
        const float* sb = g_s + b * E_;
        const float* pk = Wk + h * 128 + c;
        const float* pv = Wv + h * 128 + c;
        float ak = 0.f, av = 0.f;
#pragma unroll 8
        for (int k = half * 1024; k < half * 1024 + 1024; k++) {
            float sv = sb[k];
            ak += pk[(size_t)k * E_] * sv;
            av += pv[(size_t)k * E_] * sv;
        }
        uKp[half * 128 + c] = ak;
        uVp[half * 128 + c] = av;
        if (tid < 128) {
            bks[tid] = bk[h * 128 + tid];
            bvs[tid] = bv[h * 128 + tid];
            bqv[tid] = bq[h * 128 + tid];
        }
    }
    __syncthreads();
    if (tid < 128) {
        uK[tid] = uKp[tid] + uKp[128 + tid];
        uV[tid] = uVp[tid] + uVp[128 + tid];
    }
    __syncthreads();

    const float a = alpha[0];
    for (int i = tid; i < HD_ * HD_; i += 256) {
        int r = i >> 7, c = i & 127;
        float s1 = 0.f, s2 = 0.f;
#pragma unroll
        for (int ch = 0; ch < 4; ch++) {
            s1 += g_p1[((size_t)ch * BH_ + bh) * (HD_ * HD_) + i];
            s2 += g_p2[((size_t)ch * BH_ + bh) * (HD_ * HD_) + i];
        }
        Am[r * 129 + c] = s1 + uK[r] * bks[c] + bks[r] * uK[c]
                          + (float)S_ * bks[r] * bks[c] + ((r == c) ? a : 0.f);
        Bm[r * 129 + c] = s2 + uK[r] * bvs[c] + bks[r] * uV[c]
                          + (float)S_ * bks[r] * bvs[c];
    }
    __syncthreads();

    for (int j = 0; j < HD_; j++) {
        if (tid == 0) Am[j * 129 + j] = sqrtf(Am[j * 129 + j]);
        __syncthreads();
        float dinv = 1.0f / Am[j * 129 + j];
        int n = 127 - j;
        for (int i = tid; i < n; i += 256) Am[(j + 1 + i) * 129 + j] *= dinv;
        __syncthreads();
        int tot = n * n;
        for (int t = tid; t < tot; t += 256) {
            int ri = j + 1 + t / n, ci = j + 1 + t % n;
            Am[ri * 129 + ci] -= Am[ri * 129 + j] * Am[ci * 129 + j];
        }
        __syncthreads();
    }

    if (tid < 128) {
        const int c = tid;
        for (int i = 0; i < 128; i++) {
            float t = Bm[i * 129 + c];
            for (int j2 = 0; j2 < i; j2++) t -= Am[i * 129 + j2] * Bm[j2 * 129 + c];
            Bm[i * 129 + c] = t / Am[i * 129 + i];
        }
        for (int i = 127; i >= 0; i--) {
            float t = Bm[i * 129 + c];
            for (int j2 = i + 1; j2 < 128; j2++) t -= Am[j2 * 129 + i] * Bm[j2 * 129 + c];
            Bm[i * 129 + c] = t / Am[i * 129 + i];
        }
    }
    __syncthreads();

    if (tid < 128) {
        const int r = tid;
        float m = -1e30f;
        for (int c = 0; c < 128; c++) m = fmaxf(m, Bm[r * 129 + c]);
        float s = 0.f;
        for (int c = 0; c < 128; c++) {
            float e = expf(Bm[r * 129 + c] - m);
            Bm[r * 129 + c] = e;
            s += e;
        }
        float inv = 1.0f / s;
        sinv[r] = inv;
        for (int c = 0; c < 128; c++)
            g_score[(size_t)bh * (HD_ * HD_) + r * HD_ + c] = Bm[r * 129 + c] * inv;
    }
    __syncthreads();

    if (tid < 128) {
        const int c = tid;
        float acc = 0.f;
        for (int r = 0; r < 128; r++) acc += bqv[r] * Bm[r * 129 + c] * sinv[r];
        g_bqs[b * E_ + h * 128 + c] = acc;
    }
}

// ------ Wqs[:, hblk] = Wq[:, hblk] @ score_bh  (fp32 SIMT -> half store) ---
#define WQS_SMEM (128 * 132 * sizeof(float))
__global__ void wqs_kernel(const float* __restrict__ Wq) {
    const int bx = blockIdx.x, h = blockIdx.y, b = blockIdx.z;
    extern __shared__ float sc[];  // [128][132]
    const int tid = threadIdx.x;
    const float* sg = g_score + (size_t)(b * NH_ + h) * (HD_ * HD_);
    for (int i = tid; i < 128 * 128; i += 256) {
        int r = i >> 7, c = i & 127;
        sc[r * 132 + c] = sg[i];
    }
    __syncthreads();

    const int pr = tid >> 4, pc = tid & 15;  // 16x16 patches of 8x8
    const float* wrow = Wq + (size_t)(bx * 128 + pr * 8) * E_ + h * 128;
    float acc[8][8];
#pragma unroll
    for (int i = 0; i < 8; i++)
#pragma unroll
        for (int j = 0; j < 8; j++) acc[i][j] = 0.f;

    for (int k = 0; k < 128; k++) {
        float w8[8];
#pragma unroll
        for (int i = 0; i < 8; i++) w8[i] = wrow[(size_t)i * E_ + k];
        float4 s0 = *reinterpret_cast<const float4*>(&sc[k * 132 + pc * 8]);
        float4 s1 = *reinterpret_cast<const float4*>(&sc[k * 132 + pc * 8 + 4]);
        float s8[8] = {s0.x, s0.y, s0.z, s0.w, s1.x, s1.y, s1.z, s1.w};
#pragma unroll
        for (int i = 0; i < 8; i++)
#pragma unroll
            for (int j = 0; j < 8; j++) acc[i][j] += w8[i] * s8[j];
    }

    __half* og = g_wqsh + (size_t)b * E_ * E_ + (size_t)(bx * 128 + pr * 8) * E_
                 + h * 128 + pc * 8;
#pragma unroll
    for (int i = 0; i < 8; i++) {
        __half2* p = reinterpret_cast<__half2*>(og + (size_t)i * E_);
        p[0] = __floats2half2_rn(acc[i][0], acc[i][1]);
        p[1] = __floats2half2_rn(acc[i][2], acc[i][3]);
        p[2] = __floats2half2_rn(acc[i][4], acc[i][5]);
        p[3] = __floats2half2_rn(acc[i][6], acc[i][7]);
    }
}

// ------ b2[b][n] = sum_k bqs[b][k] * Wfc[k][n] + bfc[n]  (k-parallel) ------
__global__ void b2_build(const float* __restrict__ Wfc, const float* __restrict__ bfc) {
    __shared__ float part[2][128];
    const int tid = threadIdx.x;
    const int nl = tid & 127, half = tid >> 7;
    const int n = blockIdx.x * 128 + nl;
    const int b = blockIdx.y;
    const float* bqs = g_bqs + b * E_;
    float acc = 0.f;
#pragma unroll 8
    for (int k = half * 1024; k < half * 1024 + 1024; k++)
        acc += bqs[k] * Wfc[(size_t)k * E_ + n];
    part[half][nl] = acc;
    __syncthreads();
    if (tid < 128)
        g_b2[b * E_ + n] = part[0][nl] + part[1][nl] + bfc[n];
}

// ------ out += b2 (per batch) ----------------------------------------------
__global__ void bias_add_b2(float* __restrict__ C) {
    int i = blockIdx.x * 256 + threadIdx.x;
    int batch = i >> 21;
    int nb = i & (E_ / 4 - 1);
    float4 c = reinterpret_cast<float4*>(C)[i];
    float4 bb = reinterpret_cast<const float4*>(g_b2 + batch * E_)[nb];
    c.x += bb.x; c.y += bb.y; c.z += bb.z; c.w += bb.w;
    reinterpret_cast<float4*>(C)[i] = c;
}

// ---------------- host entry ------------------------------------------------
extern "C" void kernel_launch(void* const* d_in, const int* in_sizes, int n_in,
                              void* d_out, int out_size) {
    (void)in_sizes; (void)n_in; (void)out_size;
    const float* x     = (const float*)d_in[0];
    const float* alpha = (const float*)d_in[1];
    const float* Wq    = (const float*)d_in[2];
    const float* bq    = (const float*)d_in[3];
    const float* Wk    = (const float*)d_in[4];
    const float* bk    = (const float*)d_in[5];
    const float* Wv    = (const float*)d_in[6];
    const float* bv    = (const float*)d_in[7];
    const float* Wfc   = (const float*)d_in[8];
    const float* bfc   = (const float*)d_in[9];
    float* out = (float*)d_out;

    float *G, *yk, *w2;
    __half *Gh, *ykh, *xh, *wh, *wqsh, *w2h;
    cudaGetSymbolAddress((void**)&G,    g_G);
    cudaGetSymbolAddress((void**)&Gh,   g_Gh);
    cudaGetSymbolAddress((void**)&yk,   g_yk);
    cudaGetSymbolAddress((void**)&ykh,  g_ykh);
    cudaGetSymbolAddress((void**)&w2,   g_w2);
    cudaGetSymbolAddress((void**)&w2h,  g_w2h);
    cudaGetSymbolAddress((void**)&xh,   g_xh);
    cudaGetSymbolAddress((void**)&wh,   g_wh);
    cudaGetSymbolAddress((void**)&wqsh, g_wqsh);

    cudaFuncSetAttribute(gemm2h, cudaFuncAttributeMaxDynamicSharedMemorySize, GEMM2_SMEM);
    cudaFuncSetAttribute(syrk_h, cudaFuncAttributeMaxDynamicSharedMemorySize, SYRK_SMEM);
    cudaFuncSetAttribute(head_build_h, cudaFuncAttributeMaxDynamicSharedMemorySize, HBH_SMEM);
    cudaFuncSetAttribute(solver, cudaFuncAttributeMaxDynamicSharedMemorySize, SOLVER_SMEM);
    cudaFuncSetAttribute(wqs_kernel, cudaFuncAttributeMaxDynamicSharedMemorySize, WQS_SMEM);

    const long long EE = (long long)E_ * E_;
    const long long SE = (long long)S_ * E_;
    const int nx4 = M_TOT * E_ / 4;      // 8388608
    const int nw4 = E_ * E_ / 4;         // 1048576
    const int nG4 = B_ * E_ * E_ / 4;    // 4194304
    __half* wkh = wh + 0 * EE;
    __half* wvh = wh + 1 * EE;
    __half* wfh = wh + 2 * EE;

    // half conversions (rn rounding)
    f2h<<<nx4 / 256, 256>>>(x, xh, nx4);
    f2h<<<nw4 / 256, 256>>>(Wk, wkh, nw4);
    f2h<<<nw4 / 256, 256>>>(Wv, wvh, nw4);
    f2h<<<nw4 / 256, 256>>>(Wfc, wfh, nw4);

    // K/V side via G = X^T X (symmetric): p2 needs only yk = G @ Wk
    colsum<<<dim3(E_ / 32, B_), 256>>>(x);
    syrk_h<<<dim3(136, B_), 256, SYRK_SMEM>>>(xh);
    f2h<<<nG4 / 256, 256>>>(G, Gh, nG4);
    gemm2h<<<dim3(8, 16, B_), 256, GEMM2_SMEM>>>(Gh, wkh, wkh, yk, yk,
                                                 E_, E_, E_, EE, 0, EE, 8);
    f2h<<<nG4 / 256, 256>>>(yk, ykh, nG4);
    head_build_h<<<dim3(BH_, 4), 256, HBH_SMEM>>>(wkh, wvh);
    solver<<<BH_, 256, SOLVER_SMEM>>>(alpha, Wk, Wv, bk, bv, bq);

    // Q side collapsed: out = X @ (Wq BD(score) Wfc) + b2
    wqs_kernel<<<dim3(16, NH_, B_), 256, WQS_SMEM>>>(Wq);
    b2_build<<<dim3(E_ / 128, B_), 256>>>(Wfc, bfc);
    gemm2h<<<dim3(8, 16, B_), 256, GEMM2_SMEM>>>(wqsh, wfh, wfh, w2, w2,
                                                 E_, E_, E_, EE, 0, EE, 8);
    f2h<<<nG4 / 256, 256>>>(w2, w2h, nG4);
    gemm2h<<<dim3(8, 32, B_), 256, GEMM2_SMEM>>>(xh, w2h, w2h, out, out,
                                                 S_, E_, E_, SE, EE, SE, 8);
    bias_add_b2<<<(M_TOT * E_ / 4) / 256, 256>>>(out);
}

// round 17
// speedup vs baseline: 4.1976x; 1.0435x over previous
#include <cuda_runtime.h>
#include <cuda_fp16.h>
#include <mma.h>
#include <cstdint>

using namespace nvcuda;

// Problem constants
#define B_    4
#define S_    4096
#define E_    2048
#define NH_   16
#define HD_   128
#define M_TOT (B_ * S_)   // 16384
#define BH_   (B_ * NH_)  // 64

// ---------------- scratch (static device allocations; no cudaMalloc) -------
__device__ __half g_Gh [(size_t)B_ * E_ * E_];   // X^T X, half (direct store)
__device__ __half g_ykh[(size_t)B_ * E_ * E_];   // G @ Wk, half (direct store)
__device__ __half g_wqsh[(size_t)B_ * E_ * E_];  // Wq @ blockdiag(score), half
__device__ __half g_w2h[(size_t)B_ * E_ * E_];   // Wqs @ Wfc, half (direct)
__device__ __half g_xh [(size_t)M_TOT * E_];     // half x
__device__ __half g_wh [(size_t)4 * E_ * E_];    // half Wk, Wv, Wfc, Wq
__device__ float  g_s  [B_ * E_];                // column sums of X per batch
__device__ float  g_bqs[B_ * E_];                // score^T bq
__device__ float  g_b2 [B_ * E_];                // final fused bias
__device__ float  g_p1 [4 * BH_ * HD_ * HD_];    // partial Wk^T G Wk
__device__ float  g_p2 [4 * BH_ * HD_ * HD_];    // partial Wk^T G Wv
__device__ __half g_scoreh[BH_ * HD_ * HD_];     // softmax(solve(...)), half

// ---------------- helpers ---------------------------------------------------
__device__ __forceinline__ void cp16(void* s, const void* g) {
    unsigned sa = (unsigned)__cvta_generic_to_shared(s);
    asm volatile("cp.async.cg.shared.global [%0], [%1], 16;" :: "r"(sa), "l"(g));
}
__device__ __forceinline__ void cp_commit() {
    asm volatile("cp.async.commit_group;");
}

// ---------------- float -> half conversion pass ----------------------------
__global__ void f2h(const float* __restrict__ in, __half* __restrict__ out, int n4) {
    int i = blockIdx.x * 256 + threadIdx.x;
    if (i >= n4) return;
    float4 v = reinterpret_cast<const float4*>(in)[i];
    reinterpret_cast<__half2*>(out)[2 * i]     = __floats2half2_rn(v.x, v.y);
    reinterpret_cast<__half2*>(out)[2 * i + 1] = __floats2half2_rn(v.z, v.w);
}

// ============ fp16 GEMM: 128x256 block, 64x64 warp tile, 4-stage cp.async ==
// mode 1: half output.  mode 2: float output + per-batch bias add.
#define BM 128
#define BN 256
#define BK 32
#define NSTG 4
#define LDA 40                        // halves (32 + 8 pad)
#define LDB 264                       // halves (256 + 8 pad)
#define A_STG (BM * LDA)              // 5120 halves
#define B_STG (BK * LDB)              // 8448 halves
#define GEMM2_SMEM (NSTG * (A_STG + B_STG) * 2)   // 108544 B

__global__ __launch_bounds__(256, 1)
void gemm2h(const __half* __restrict__ A,
            const __half* __restrict__ W, const __half* __restrict__ Wb,
            void* __restrict__ C, void* __restrict__ Cb,
            const float* __restrict__ bias,
            int M, int N, int K,
            long long sA, long long sB, long long sC, int nbx, int mode) {
    A += (long long)blockIdx.z * sA;
    int bn = blockIdx.x;
    const __half* Wsel; void* Csel;
    if (bn >= nbx) { Wsel = Wb; Csel = Cb; bn -= nbx; }
    else           { Wsel = W;  Csel = C; }
    Wsel += (long long)blockIdx.z * sB;
    const size_t zoff = (size_t)blockIdx.z * sC;

    extern __shared__ __half smh[];
    __half* As = smh;
    __half* Bs = smh + NSTG * A_STG;
    const int tid = threadIdx.x;
    const int lane = tid & 31;
    const int bm = blockIdx.y;
    const int wid = tid >> 5;
    const int wr = wid >> 2, wc = wid & 3;   // 2x4 warp grid, warp tile 64x64

    wmma::fragment<wmma::accumulator, 16, 16, 16, float> acc[4][4];
#pragma unroll
    for (int i = 0; i < 4; i++)
#pragma unroll
        for (int j = 0; j < 4; j++) wmma::fill_fragment(acc[i][j], 0.0f);

    const int KT = K / BK;
    const __half* Ab = A + (size_t)bm * BM * K;
    const __half* Bb = Wsel + (size_t)bn * BN;

    auto load_stage = [&](int kt, int buf) {
        __half* Asb = As + buf * A_STG;
        const __half* Ag = Ab + kt * BK;
#pragma unroll
        for (int p = 0; p < 2; p++) {
            int id = tid + p * 256;
            int r = id >> 2, c = (id & 3) << 3;
            cp16(Asb + r * LDA + c, Ag + (size_t)r * K + c);
        }
        __half* Bsb = Bs + buf * B_STG;
        const __half* Bg = Bb + (size_t)kt * BK * N;
#pragma unroll
        for (int p = 0; p < 4; p++) {
            int id = tid + p * 256;
            int r = id >> 5, c = (id & 31) << 3;
            cp16(Bsb + r * LDB + c, Bg + (size_t)r * N + c);
        }
        cp_commit();
    };

    load_stage(0, 0); load_stage(1, 1); load_stage(2, 2);

    for (int kt = 0; kt < KT; kt++) {
        if (kt + 2 < KT)      asm volatile("cp.async.wait_group 2;");
        else if (kt + 1 < KT) asm volatile("cp.async.wait_group 1;");
        else                  asm volatile("cp.async.wait_group 0;");
        __syncthreads();
        const int buf = kt % NSTG;
        const __half* Asb = As + buf * A_STG;
        const __half* Bsb = Bs + buf * B_STG;
#pragma unroll
        for (int ks = 0; ks < BK; ks += 16) {
            wmma::fragment<wmma::matrix_a, 16, 16, 16, __half, wmma::row_major> af[4];
            wmma::fragment<wmma::matrix_b, 16, 16, 16, __half, wmma::row_major> bf[4];
#pragma unroll
            for (int i = 0; i < 4; i++)
                wmma::load_matrix_sync(af[i], Asb + (wr * 64 + i * 16) * LDA + ks, LDA);
#pragma unroll
            for (int j = 0; j < 4; j++)
                wmma::load_matrix_sync(bf[j], Bsb + ks * LDB + wc * 64 + j * 16, LDB);
#pragma unroll
            for (int i = 0; i < 4; i++)
#pragma unroll
                for (int j = 0; j < 4; j++)
                    wmma::mma_sync(acc[i][j], af[i], bf[j], acc[i][j]);
        }
        if (kt + 3 < KT) load_stage(kt + 3, (kt + 3) % NSTG);
        __syncthreads();
    }
    // (loop-bottom __syncthreads: smem now free for staging)

    float* stg = reinterpret_cast<float*>(smh) + wid * 1024;  // 16x64 per warp
    const size_t cidx = zoff + (size_t)(bm * BM + wr * 64) * N + (size_t)bn * BN + wc * 64;

    if (mode == 1) {
        __half* Cgh = reinterpret_cast<__half*>(Csel) + cidx;
#pragma unroll
        for (int i = 0; i < 4; i++) {
            __syncwarp();
#pragma unroll
            for (int j = 0; j < 4; j++)
                wmma::store_matrix_sync(stg + j * 16, acc[i][j], 64, wmma::mem_row_major);
            __syncwarp();
#pragma unroll
            for (int e = lane; e < 16 * 32; e += 32) {   // 16 rows x 32 half2
                int r = e >> 5, c2 = e & 31;
                float2 v = reinterpret_cast<float2*>(stg + r * 64)[c2];
                reinterpret_cast<__half2*>(Cgh + (size_t)(i * 16 + r) * N)[c2] =
                    __floats2half2_rn(v.x, v.y);
            }
        }
    } else {  // mode 2: float + bias
        float* Cg = reinterpret_cast<float*>(Csel) + cidx;
        const float* bz = bias + blockIdx.z * E_ + bn * BN + wc * 64;
#pragma unroll
        for (int i = 0; i < 4; i++) {
            __syncwarp();
#pragma unroll
            for (int j = 0; j < 4; j++)
                wmma::store_matrix_sync(stg + j * 16, acc[i][j], 64, wmma::mem_row_major);
            __syncwarp();
#pragma unroll
            for (int e = lane; e < 16 * 16; e += 32) {   // 16 rows x 16 float4
                int r = e >> 4, c4 = e & 15;
                float4 v = reinterpret_cast<float4*>(stg + r * 64)[c4];
                float4 bb = *reinterpret_cast<const float4*>(bz + c4 * 4);
                v.x += bb.x; v.y += bb.y; v.z += bb.z; v.w += bb.w;
                reinterpret_cast<float4*>(Cg + (size_t)(i * 16 + r) * N)[c4] = v;
            }
        }
    }
}

// ---------------- column sums: s[b][e] = sum_m x[b][m][e] -------------------
__global__ void colsum(const float* __restrict__ x) {
    __shared__ float red[256];
    const int tid = threadIdx.x;
    const int tx = tid & 31, ty = tid >> 5;
    const int e = blockIdx.x * 32 + tx;
    const int b = blockIdx.y;
    const float* xb = x + (size_t)b * S_ * E_ + e;
    float acc = 0.f;
    for (int m = ty; m < S_; m += 8) acc += xb[(size_t)m * E_];
    red[ty * 32 + tx] = acc;
    __syncthreads();
    if (ty == 0) {
        float t = 0.f;
#pragma unroll
        for (int i = 0; i < 8; i++) t += red[i * 32 + tx];
        g_s[b * E_ + e] = t;
    }
}

// ------- G = Xh^T Xh (fp16 MMA; direct half store + mirrored tile) ---------
#define SY_STG (32 * 136)                       // halves per operand stage
#define SYRK_SMEM (2 * 2 * SY_STG * 2)          // 34816 B
__global__ __launch_bounds__(256, 2)
void syrk_h(const __half* __restrict__ x) {
    int rem = blockIdx.x, i = 0;
    while (rem >= 16 - i) { rem -= (16 - i); i++; }
    const int j = i + rem;
    const int b = blockIdx.y;
    extern __shared__ __half smh[];
    __half* As = smh;
    __half* Bs = smh + 2 * SY_STG;
    const int tid = threadIdx.x;
    const int lane = tid & 31;
    const int wid = tid >> 5, wr = wid >> 1, wc = wid & 1;

    const __half* ai = x + (size_t)b * S_ * E_ + i * 128;
    const __half* bj = x + (size_t)b * S_ * E_ + j * 128;

    wmma::fragment<wmma::accumulator, 16, 16, 16, float> acc[2][4];
#pragma unroll
    for (int p = 0; p < 2; p++)
#pragma unroll
        for (int q = 0; q < 4; q++) wmma::fill_fragment(acc[p][q], 0.0f);

    auto load_stage = [&](int it, int buf) {
        const int ss = it * 32;
#pragma unroll
        for (int p = 0; p < 2; p++) {
            int id = tid + p * 256;
            int r = id >> 4, c = (id & 15) << 3;
            cp16(As + buf * SY_STG + r * 136 + c, ai + (size_t)(ss + r) * E_ + c);
            cp16(Bs + buf * SY_STG + r * 136 + c, bj + (size_t)(ss + r) * E_ + c);
        }
        cp_commit();
    };

    const int IT = S_ / 32;   // 128
    load_stage(0, 0);
    for (int it = 0; it < IT; it++) {
        if (it + 1 < IT) { load_stage(it + 1, (it + 1) & 1);
                           asm volatile("cp.async.wait_group 1;"); }
        else             { asm volatile("cp.async.wait_group 0;"); }
        __syncthreads();
        const __half* Asb = As + (it & 1) * SY_STG;
        const __half* Bsb = Bs + (it & 1) * SY_STG;
#pragma unroll
        for (int ks = 0; ks < 32; ks += 16) {
            wmma::fragment<wmma::matrix_a, 16, 16, 16, __half, wmma::col_major> af[2];
#pragma unroll
            for (int p = 0; p < 2; p++)
                wmma::load_matrix_sync(af[p], Asb + ks * 136 + wr * 32 + p * 16, 136);
#pragma unroll
            for (int q = 0; q < 4; q++) {
                wmma::fragment<wmma::matrix_b, 16, 16, 16, __half, wmma::row_major> bf;
                wmma::load_matrix_sync(bf, Bsb + ks * 136 + wc * 64 + q * 16, 136);
                wmma::mma_sync(acc[0][q], af[0], bf, acc[0][q]);
                wmma::mma_sync(acc[1][q], af[1], bf, acc[1][q]);
            }
        }
        __syncthreads();
    }
    // smem free after loop-bottom sync; per-warp 16x16 staging
    float* stg = reinterpret_cast<float*>(smh) + wid * 256;
    __half* Gb = g_Gh + (size_t)b * E_ * E_;
#pragma unroll
    for (int p = 0; p < 2; p++)
#pragma unroll
        for (int q = 0; q < 4; q++) {
            __syncwarp();
            wmma::store_matrix_sync(stg, acc[p][q], 16, wmma::mem_row_major);
            __syncwarp();
            const int rr = i * 128 + wr * 32 + p * 16;
            const int cc = j * 128 + wc * 64 + q * 16;
#pragma unroll
            for (int e = lane; e < 16 * 8; e += 32) {   // 16 rows x 8 half2
                int r = e >> 3, c2 = e & 7;
                float2 v = reinterpret_cast<float2*>(stg + r * 16)[c2];
                reinterpret_cast<__half2*>(Gb + (size_t)(rr + r) * E_ + cc)[c2] =
                    __floats2half2_rn(v.x, v.y);
            }
            if (i != j) {
#pragma unroll
                for (int e = lane; e < 16 * 8; e += 32) {  // transposed tile
                    int r = e >> 3, c2 = e & 7;
                    __half2 h2 = __floats2half2_rn(stg[(2 * c2) * 16 + r],
                                                   stg[(2 * c2 + 1) * 16 + r]);
                    reinterpret_cast<__half2*>(Gb + (size_t)(cc + r) * E_ + rr)[c2] = h2;
                }
            }
        }
}

// --------- per-head raw mats via symmetry (fp16):
//   p1_h = yk_h^T @ Wk_h,  p2_h = yk_h^T @ Wv_h
#define HBH_STG (3 * 32 * 136)                 // halves
#define HBH_SMEM (2 * HBH_STG * 2)             // 52224 B
__global__ void head_build_h(const __half* __restrict__ wkh,
                             const __half* __restrict__ wvh) {
    const int bh = blockIdx.x, chunk = blockIdx.y;
    const int b = bh >> 4, h = bh & 15;
    extern __shared__ __half smh[];
    const int tid = threadIdx.x;
    const int wid = tid >> 5, wr = wid >> 1, wc = wid & 1;

    const __half* ykb = g_ykh + (size_t)b * E_ * E_ + h * 128;
    const __half* kb  = wkh + h * 128;
    const __half* vb  = wvh + h * 128;
    const int k0 = chunk * 512;

    wmma::fragment<wmma::accumulator, 16, 16, 16, float> acck[2][4], accv[2][4];
#pragma unroll
    for (int p = 0; p < 2; p++)
#pragma unroll
        for (int q = 0; q < 4; q++) {
            wmma::fill_fragment(acck[p][q], 0.0f);
            wmma::fill_fragment(accv[p][q], 0.0f);
        }

    auto load_stage = [&](int it, int buf) {
        __half* base = smh + buf * HBH_STG;
        const int ss = k0 + it * 32;
#pragma unroll
        for (int p = 0; p < 2; p++) {
            int id = tid + p * 256;
            int r = id >> 4, c = (id & 15) << 3;
            size_t row = (size_t)(ss + r) * E_;
            cp16(base + r * 136 + c,        ykb + row + c);
            cp16(base + 4352 + r * 136 + c, kb + row + c);
            cp16(base + 8704 + r * 136 + c, vb + row + c);
        }
        cp_commit();
    };

    const int IT = 16;
    load_stage(0, 0);
    for (int it = 0; it < IT; it++) {
        if (it + 1 < IT) { load_stage(it + 1, (it + 1) & 1);
                           asm volatile("cp.async.wait_group 1;"); }
        else             { asm volatile("cp.async.wait_group 0;"); }
        __syncthreads();
        const __half* base = smh + (it & 1) * HBH_STG;
        const __half* Ys = base;
        const __half* Ks = base + 4352;
        const __half* Vs = base + 8704;
#pragma unroll
        for (int ks = 0; ks < 32; ks += 16) {
            wmma::fragment<wmma::matrix_a, 16, 16, 16, __half, wmma::col_major> af[2];
#pragma unroll
            for (int p = 0; p < 2; p++)
                wmma::load_matrix_sync(af[p], Ys + ks * 136 + wr * 32 + p * 16, 136);
#pragma unroll
            for (int q = 0; q < 4; q++) {
                wmma::fragment<wmma::matrix_b, 16, 16, 16, __half, wmma::row_major> bf;
                wmma::load_matrix_sync(bf, Ks + ks * 136 + wc * 64 + q * 16, 136);
                wmma::mma_sync(acck[0][q], af[0], bf, acck[0][q]);
                wmma::mma_sync(acck[1][q], af[1], bf, acck[1][q]);
                wmma::load_matrix_sync(bf, Vs + ks * 136 + wc * 64 + q * 16, 136);
                wmma::mma_sync(accv[0][q], af[0], bf, accv[0][q]);
                wmma::mma_sync(accv[1][q], af[1], bf, accv[1][q]);
            }
        }
        __syncthreads();
    }
    float* p1 = g_p1 + ((size_t)chunk * BH_ + bh) * (HD_ * HD_);
    float* p2 = g_p2 + ((size_t)chunk * BH_ + bh) * (HD_ * HD_);
#pragma unroll
    for (int p = 0; p < 2; p++)
#pragma unroll
        for (int q = 0; q < 4; q++) {
            wmma::store_matrix_sync(p1 + (wr * 32 + p * 16) * HD_ + wc * 64 + q * 16,
                                    acck[p][q], HD_, wmma::mem_row_major);
            wmma::store_matrix_sync(p2 + (wr * 32 + p * 16) * HD_ + wc * 64 + q * 16,
                                    accv[p][q], HD_, wmma::mem_row_major);
        }
}

// -------- solver: bias rank-1s + alpha*I, Cholesky solve, softmax, bqs -----
#define SOLVER_SMEM ((2 * 128 * 129 + 6 * 128 + 512) * sizeof(float))
__global__ void solver(const float* __restrict__ alpha,
                       const float* __restrict__ Wk, const float* __restrict__ Wv,
                       const float* __restrict__ bk, const float* __restrict__ bv,
                       const float* __restrict__ bq) {
    const int bh = blockIdx.x;
    const int b = bh >> 4, h = bh & 15;
    const int tid = threadIdx.x;
    extern __shared__ float sm[];
    float* Am  = sm;
    float* Bm  = Am + 128 * 129;
    float* uK  = Bm + 128 * 129;
    float* uV  = uK + 128;
    float* bks = uV + 128;
    float* bvs = bks + 128;
    float* bqv = bvs + 128;
    float* sinv = bqv + 128;
    float* uKp = sinv + 128;
    float* uVp = uKp + 256;

    {
        const int c = tid & 127, half = tid >> 7;
        const float* sb = g_s + b * E_;
        const float* pk = Wk + h * 128 + c;
        const float* pv = Wv + h * 128 + c;
        float ak = 0.f, av = 0.f;
#pragma unroll 8
        for (int k = half * 1024; k < half * 1024 + 1024; k++) {
            float sv = sb[k];
            ak += pk[(size_t)k * E_] * sv;
            av += pv[(size_t)k * E_] * sv;
        }
        uKp[half * 128 + c] = ak;
        uVp[half * 128 + c] = av;
        if (tid < 128) {
            bks[tid] = bk[h * 128 + tid];
            bvs[tid] = bv[h * 128 + tid];
            bqv[tid] = bq[h * 128 + tid];
        }
    }
    __syncthreads();
    if (tid < 128) {
        uK[tid] = uKp[tid] + uKp[128 + tid];
        uV[tid] = uVp[tid] + uVp[128 + tid];
    }
    __syncthreads();

    const float a = alpha[0];
    for (int i = tid; i < HD_ * HD_; i += 256) {
        int r = i >> 7, c = i & 127;
        float s1 = 0.f, s2 = 0.f;
#pragma unroll
        for (int ch = 0; ch < 4; ch++) {
            s1 += g_p1[((size_t)ch * BH_ + bh) * (HD_ * HD_) + i];
            s2 += g_p2[((size_t)ch * BH_ + bh) * (HD_ * HD_) + i];
        }
        Am[r * 129 + c] = s1 + uK[r] * bks[c] + bks[r] * uK[c]
                          + (float)S_ * bks[r] * bks[c] + ((r == c) ? a : 0.f);
        Bm[r * 129 + c] = s2 + uK[r] * bvs[c] + bks[r] * uV[c]
                          + (float)S_ * bks[r] * bvs[c];
    }
    __syncthreads();

    for (int j = 0; j < HD_; j++) {
        if (tid == 0) Am[j * 129 + j] = sqrtf(Am[j * 129 + j]);
        __syncthreads();
        float dinv = 1.0f / Am[j * 129 + j];
        int n = 127 - j;
        for (int i = tid; i < n; i += 256) Am[(j + 1 + i) * 129 + j] *= dinv;
        __syncthreads();
        int tot = n * n;
        for (int t = tid; t < tot; t += 256) {
            int ri = j + 1 + t / n, ci = j + 1 + t % n;
            Am[ri * 129 + ci] -= Am[ri * 129 + j] * Am[ci * 129 + j];
        }
        __syncthreads();
    }

    if (tid < 128) {
        const int c = tid;
        for (int i = 0; i < 128; i++) {
            float t = Bm[i * 129 + c];
            for (int j2 = 0; j2 < i; j2++) t -= Am[i * 129 + j2] * Bm[j2 * 129 + c];
            Bm[i * 129 + c] = t / Am[i * 129 + i];
        }
        for (int i = 127; i >= 0; i--) {
            float t = Bm[i * 129 + c];
            for (int j2 = i + 1; j2 < 128; j2++) t -= Am[j2 * 129 + i] * Bm[j2 * 129 + c];
            Bm[i * 129 + c] = t / Am[i * 129 + i];
        }
    }
    __syncthreads();

    if (tid < 128) {
        const int r = tid;
        float m = -1e30f;
        for (int c = 0; c < 128; c++) m = fmaxf(m, Bm[r * 129 + c]);
        float s = 0.f;
        for (int c = 0; c < 128; c++) {
            float e = expf(Bm[r * 129 + c] - m);
            Bm[r * 129 + c] = e;
            s += e;
        }
        float inv = 1.0f / s;
        sinv[r] = inv;
        for (int c = 0; c < 128; c++)
            g_scoreh[(size_t)bh * (HD_ * HD_) + r * HD_ + c] =
                __float2half_rn(Bm[r * 129 + c] * inv);
    }
    __syncthreads();

    if (tid < 128) {
        const int c = tid;
        float acc = 0.f;
        for (int r = 0; r < 128; r++) acc += bqv[r] * Bm[r * 129 + c] * sinv[r];
        g_bqs[b * E_ + h * 128 + c] = acc;
    }
}

// ------ Wqs[:, hblk] = Wq[:, hblk] @ score_bh  (fp16 wmma, half out) -------
#define WQSH_SMEM (2 * 128 * 136 * 2)   // 69632 B
__global__ void wqs_h(const __half* __restrict__ wqh) {
    const int bx = blockIdx.x, h = blockIdx.y, b = blockIdx.z;
    extern __shared__ __half smh[];
    __half* As = smh;              // Wq tile 128x128 (ld 136)
    __half* Bs = smh + 128 * 136;  // score 128x128 (ld 136)
    const int tid = threadIdx.x;
    const int lane = tid & 31;
    const int wid = tid >> 5;
    const int wr = wid >> 2, wc = wid & 3;   // 2x4 grid, warp tile 64x32

    const __half* ag = wqh + (size_t)(bx * 128) * E_ + h * 128;
    const __half* sg = g_scoreh + (size_t)(b * NH_ + h) * (HD_ * HD_);
#pragma unroll
    for (int p = 0; p < 8; p++) {
        int id = tid + p * 256;
        int r = id >> 4, c = (id & 15) << 3;
        cp16(As + r * 136 + c, ag + (size_t)r * E_ + c);
        cp16(Bs + r * 136 + c, sg + r * 128 + c);
    }
    cp_commit();
    asm volatile("cp.async.wait_group 0;");
    __syncthreads();

    wmma::fragment<wmma::accumulator, 16, 16, 16, float> acc[4][2];
#pragma unroll
    for (int i = 0; i < 4; i++)
#pragma unroll
        for (int j = 0; j < 2; j++) wmma::fill_fragment(acc[i][j], 0.0f);

#pragma unroll
    for (int ks = 0; ks < 128; ks += 16) {
        wmma::fragment<wmma::matrix_a, 16, 16, 16, __half, wmma::row_major> af[4];
        wmma::fragment<wmma::matrix_b, 16, 16, 16, __half, wmma::row_major> bf[2];
#pragma unroll
        for (int i = 0; i < 4; i++)
            wmma::load_matrix_sync(af[i], As + (wr * 64 + i * 16) * 136 + ks, 136);
#pragma unroll
        for (int j = 0; j < 2; j++)
            wmma::load_matrix_sync(bf[j], Bs + ks * 136 + wc * 32 + j * 16, 136);
#pragma unroll
        for (int i = 0; i < 4; i++)
#pragma unroll
            for (int j = 0; j < 2; j++)
                wmma::mma_sync(acc[i][j], af[i], bf[j], acc[i][j]);
    }
    __syncthreads();   // all warps done reading smem before staging reuse

    float* stg = reinterpret_cast<float*>(smh) + wid * 512;  // 16x32 per warp
    __half* og = g_wqsh + (size_t)b * E_ * E_ + (size_t)(bx * 128 + wr * 64) * E_
                 + h * 128 + wc * 32;
#pragma unroll
    for (int i = 0; i < 4; i++) {
        __syncwarp();
#pragma unroll
        for (int j = 0; j < 2; j++)
            wmma::store_matrix_sync(stg + j * 16, acc[i][j], 32, wmma::mem_row_major);
        __syncwarp();
#pragma unroll
        for (int e = lane; e < 16 * 16; e += 32) {  // 16 rows x 16 half2
            int r = e >> 4, c2 = e & 15;
            float2 v = reinterpret_cast<float2*>(stg + r * 32)[c2];
            reinterpret_cast<__half2*>(og + (size_t)(i * 16 + r) * E_)[c2] =
                __floats2half2_rn(v.x, v.y);
        }
    }
}

// ------ b2[b][n] = sum_k bqs[b][k] * Wfc[k][n] + bfc[n]  (k-parallel) ------
__global__ void b2_build(const float* __restrict__ Wfc, const float* __restrict__ bfc) {
    __shared__ float part[2][128];
    const int tid = threadIdx.x;
    const int nl = tid & 127, half = tid >> 7;
    const int n = blockIdx.x * 128 + nl;
    const int b = blockIdx.y;
    const float* bqs = g_bqs + b * E_;
    float acc = 0.f;
#pragma unroll 8
    for (int k = half * 1024; k < half * 1024 + 1024; k++)
        acc += bqs[k] * Wfc[(size_t)k * E_ + n];
    part[half][nl] = acc;
    __syncthreads();
    if (tid < 128)
        g_b2[b * E_ + n] = part[0][nl] + part[1][nl] + bfc[n];
}

// ---------------- host entry ------------------------------------------------
extern "C" void kernel_launch(void* const* d_in, const int* in_sizes, int n_in,
                              void* d_out, int out_size) {
    (void)in_sizes; (void)n_in; (void)out_size;
    const float* x     = (const float*)d_in[0];
    const float* alpha = (const float*)d_in[1];
    const float* Wq    = (const float*)d_in[2];
    const float* bq    = (const float*)d_in[3];
    const float* Wk    = (const float*)d_in[4];
    const float* bk    = (const float*)d_in[5];
    const float* Wv    = (const float*)d_in[6];
    const float* bv    = (const float*)d_in[7];
    const float* Wfc   = (const float*)d_in[8];
    const float* bfc   = (const float*)d_in[9];
    float* out = (float*)d_out;

    __half *Gh, *ykh, *xh, *wh, *wqsh, *w2h;
    float* b2;
    cudaGetSymbolAddress((void**)&Gh,   g_Gh);
    cudaGetSymbolAddress((void**)&ykh,  g_ykh);
    cudaGetSymbolAddress((void**)&w2h,  g_w2h);
    cudaGetSymbolAddress((void**)&xh,   g_xh);
    cudaGetSymbolAddress((void**)&wh,   g_wh);
    cudaGetSymbolAddress((void**)&wqsh, g_wqsh);
    cudaGetSymbolAddress((void**)&b2,   g_b2);

    cudaFuncSetAttribute(gemm2h, cudaFuncAttributeMaxDynamicSharedMemorySize, GEMM2_SMEM);
    cudaFuncSetAttribute(syrk_h, cudaFuncAttributeMaxDynamicSharedMemorySize, SYRK_SMEM);
    cudaFuncSetAttribute(head_build_h, cudaFuncAttributeMaxDynamicSharedMemorySize, HBH_SMEM);
    cudaFuncSetAttribute(solver, cudaFuncAttributeMaxDynamicSharedMemorySize, SOLVER_SMEM);
    cudaFuncSetAttribute(wqs_h, cudaFuncAttributeMaxDynamicSharedMemorySize, WQSH_SMEM);

    const long long EE = (long long)E_ * E_;
    const long long SE = (long long)S_ * E_;
    const int nx4 = M_TOT * E_ / 4;
    const int nw4 = E_ * E_ / 4;
    __half* wkh = wh + 0 * EE;
    __half* wvh = wh + 1 * EE;
    __half* wfh = wh + 2 * EE;
    __half* wqh = wh + 3 * EE;

    // half conversions
    f2h<<<nx4 / 256, 256>>>(x, xh, nx4);
    f2h<<<nw4 / 256, 256>>>(Wk, wkh, nw4);
    f2h<<<nw4 / 256, 256>>>(Wv, wvh, nw4);
    f2h<<<nw4 / 256, 256>>>(Wfc, wfh, nw4);
    f2h<<<nw4 / 256, 256>>>(Wq, wqh, nw4);

    // K/V side via G = X^T X (symmetric): p2 needs only yk = G @ Wk
    colsum<<<dim3(E_ / 32, B_), 256>>>(x);
    syrk_h<<<dim3(136, B_), 256, SYRK_SMEM>>>(xh);
    gemm2h<<<dim3(8, 16, B_), 256, GEMM2_SMEM>>>(Gh, wkh, wkh, ykh, ykh, nullptr,
                                                 E_, E_, E_, EE, 0, EE, 8, 1);
    head_build_h<<<dim3(BH_, 4), 256, HBH_SMEM>>>(wkh, wvh);
    solver<<<BH_, 256, SOLVER_SMEM>>>(alpha, Wk, Wv, bk, bv, bq);

    // Q side collapsed: out = X @ (Wq BD(score) Wfc) + b2
    wqs_h<<<dim3(16, NH_, B_), 256, WQSH_SMEM>>>(wqh);
    b2_build<<<dim3(E_ / 128, B_), 256>>>(Wfc, bfc);
    gemm2h<<<dim3(8, 16, B_), 256, GEMM2_SMEM>>>(wqsh, wfh, wfh, w2h, w2h, nullptr,
                                                 E_, E_, E_, EE, 0, EE, 8, 1);
    gemm2h<<<dim3(8, 32, B_), 256, GEMM2_SMEM>>>(xh, w2h, w2h, out, out, b2,
                                                 S_, E_, E_, SE, EE, SE, 8, 2);
}